// round 1
// baseline (speedup 1.0000x reference)
#include <cuda_runtime.h>
#include <math.h>

// ---------------- problem constants ----------------
#define BB   8
#define TT   1024
#define BTOK (BB*TT)          // 8192
#define N4   4
#define K3   3
#define DH   128
#define DD   896              // S*DH
#define NDD  3584             // N*D
#define HID  3584             // 4*D
#define IOD  1024
#define RNK  64
#define NH   12               // N*K heads
#define EPSF 1e-5f

// ---------------- device scratch ----------------
__device__ float g_beta;
__device__ int   g_slot[3];
__device__ int   g_invp[3][4];

__device__ float g_h[BTOK*RNK];
__device__ float g_z1[(size_t)BTOK*NDD];               // z0 -> z1 -> z2 in place
__device__ float g_hm[(size_t)BTOK*NDD];               // mixer LN out, then dec LN out (same size)
__device__ float g_hidden[(size_t)BTOK*4*HID];         // 32768 x 3584
__device__ float g_xh[(size_t)BTOK*NH*DH];             // LN'ed heads
__device__ float g_q[(size_t)BB*NH*TT*DH];
__device__ float g_k[(size_t)BB*NH*TT*DH];
__device__ float g_v[(size_t)BB*NH*TT*DH];
__device__ float g_sc[(size_t)BB*NH*TT*TT];            // scores / probs
__device__ float g_dec[BTOK*RNK];

// ---------------- scalar / table prologue ----------------
__global__ void k_scalars(const float* beta, const int* phase) {
    g_beta = *beta;
    int ph = *phase;
    int off = 0;
    const int sc[3] = {1, 2, 4};
    for (int k = 0; k < 3; k++) {
        int s = sc[k];
        int j = ph % s;
        g_slot[k] = off + j;
        off += s;
        int alpha = 4 / s;
        for (int i = 0; i < 4; i++) {
            int p = (i + alpha * j) & 3;   // PERM[k][i]
            g_invp[k][p] = i;              // INV[k][p] = i
        }
    }
}

// ---------------- block reductions ----------------
template<int W>
__device__ __forceinline__ float block_sum(float x, float* red) {
#pragma unroll
    for (int o = 16; o > 0; o >>= 1) x += __shfl_xor_sync(0xffffffffu, x, o);
    __syncthreads();
    if ((threadIdx.x & 31) == 0) red[threadIdx.x >> 5] = x;
    __syncthreads();
    float s = 0.f;
#pragma unroll
    for (int i = 0; i < W; i++) s += red[i];
    return s;
}
template<int W>
__device__ __forceinline__ float block_max(float x, float* red) {
#pragma unroll
    for (int o = 16; o > 0; o >>= 1) x = fmaxf(x, __shfl_xor_sync(0xffffffffu, x, o));
    __syncthreads();
    if ((threadIdx.x & 31) == 0) red[threadIdx.x >> 5] = x;
    __syncthreads();
    float s = -1e30f;
#pragma unroll
    for (int i = 0; i < W; i++) s = fmaxf(s, red[i]);
    return s;
}

// ---------------- epilogue functors ----------------
struct EpiH {
    __device__ void operator()(int m, int n, int, float v) const { g_h[m*RNK + n] = v; }
};
struct EpiBase {   // broadcast base row to all 4 n-slots of z0
    __device__ void operator()(int m, int n, int, float v) const {
        size_t base = (size_t)m * NDD + n;
        g_z1[base] = v; g_z1[base + DD] = v; g_z1[base + 2*DD] = v; g_z1[base + 3*DD] = v;
    }
};
struct EpiDelta {  // z0 += beta * delta  (z1 viewed as 8192 x 3584)
    __device__ void operator()(int m, int n, int, float v) const {
        g_z1[(size_t)m * NDD + n] += g_beta * v;
    }
};
struct EpiQKV {    // scatter qkv into head-permuted q/k/v layouts
    __device__ void operator()(int m, int n, int bz, float v) const {
        int b = m >> 10, t = m & 1023;
        int kk = bz >> 2, ns = bz & 3;
        int h = g_invp[kk][ns] * 3 + kk;    // head = n_out*K + k
        float* dst; int e = n;
        if (e < DH)            { dst = g_q; }
        else if (e < 2*DH)     { dst = g_k; e -= DH; }
        else                   { dst = g_v; e -= 2*DH; }
        dst[(((size_t)b * NH + h) * TT + t) * DH + e] = v;
    }
};
struct EpiScore {  // scale + causal mask
    __device__ void operator()(int m, int n, int bz, float v) const {
        g_sc[((size_t)bz * TT + m) * TT + n] =
            (n <= m) ? v * 0.088388347648318447f : -1e9f;
    }
};
struct EpiPV {     // accumulate attention output into z1 slot
    __device__ void operator()(int m, int n, int bz, float v) const {
        int b = bz / NH, h = bz % NH;
        int kk = h % 3, nn = h / 3;
        int slot = g_slot[kk];
        g_z1[(((size_t)(b * TT + m)) * N4 + nn) * DD + slot * DH + n] += v;
    }
};
struct EpiGelu {
    const float* b1;
    __device__ void operator()(int m, int n, int, float v) const {
        float u = v + b1[n];
        g_hidden[(size_t)m * HID + n] = 0.5f * u * (1.f + erff(u * 0.70710678118654752f));
    }
};
struct EpiMix2 {   // z2 = z1 + m
    const float* b2;
    __device__ void operator()(int m, int n, int, float v) const {
        g_z1[(size_t)m * DD + n] += v + b2[n];
    }
};
struct EpiDecD {
    __device__ void operator()(int m, int n, int, float v) const { g_dec[m*RNK + n] = v; }
};
struct EpiOut {
    float* out;
    __device__ void operator()(int m, int n, int, float v) const { out[(size_t)m * IOD + n] = v; }
};

// ---------------- tiled GEMM (128x128x16, 8x8/thread) ----------------
// BT_=true : B is (N x K) row-major (NT, dot over contiguous k of both)
// BT_=false: B is (K x N) row-major (NN)
// CSKIP: skip K-loop for fully-causal-masked score blocks
// CKLIM: clip K-loop to m0+128 (PV over causal probs)
template<bool BT_, bool CSKIP, bool CKLIM, class Epi>
__global__ void __launch_bounds__(256)
gemm(const float* __restrict__ A, const float* __restrict__ B,
     int M, int N, int Kd, int lda, int ldb, long sA, long sB, Epi epi)
{
    const int bz = blockIdx.z;
    A += (size_t)bz * sA;
    B += (size_t)bz * sB;
    const int m0 = blockIdx.y * 128, n0 = blockIdx.x * 128;
    const int tid = threadIdx.x, tx = tid & 15, ty = tid >> 4;

    __shared__ float As[16][132];
    __shared__ float Bs[16][132];

    float acc[8][8];
#pragma unroll
    for (int i = 0; i < 8; i++)
#pragma unroll
        for (int j = 0; j < 8; j++) acc[i][j] = 0.f;

    bool full = !(CSKIP && n0 >= m0 + 128);
    if (full) {
        int kEnd = CKLIM ? ((Kd < m0 + 128) ? Kd : (m0 + 128)) : Kd;
        for (int k0 = 0; k0 < kEnd; k0 += 16) {
#pragma unroll
            for (int i = 0; i < 8; i++) {
                int idx = i * 256 + tid;
                int mm = idx >> 4, kk = idx & 15;
                int gm = m0 + mm, gk = k0 + kk;
                As[kk][mm] = (gm < M && gk < Kd) ? A[(size_t)gm * lda + gk] : 0.f;
            }
            if (BT_) {
#pragma unroll
                for (int i = 0; i < 8; i++) {
                    int idx = i * 256 + tid;
                    int nn = idx >> 4, kk = idx & 15;
                    int gn = n0 + nn, gk = k0 + kk;
                    Bs[kk][nn] = (gn < N && gk < Kd) ? B[(size_t)gn * ldb + gk] : 0.f;
                }
            } else {
#pragma unroll
                for (int i = 0; i < 8; i++) {
                    int idx = i * 256 + tid;
                    int nn = idx & 127, kk = idx >> 7;
                    int gn = n0 + nn, gk = k0 + kk;
                    Bs[kk][nn] = (gn < N && gk < Kd) ? B[(size_t)gk * ldb + gn] : 0.f;
                }
            }
            __syncthreads();
#pragma unroll
            for (int kk = 0; kk < 16; kk++) {
                float a[8], b[8];
#pragma unroll
                for (int i = 0; i < 8; i++) a[i] = As[kk][ty * 8 + i];
#pragma unroll
                for (int j = 0; j < 8; j++) b[j] = Bs[kk][tx * 8 + j];
#pragma unroll
                for (int i = 0; i < 8; i++)
#pragma unroll
                    for (int j = 0; j < 8; j++) acc[i][j] = fmaf(a[i], b[j], acc[i][j]);
            }
            __syncthreads();
        }
    }
#pragma unroll
    for (int i = 0; i < 8; i++) {
        int gm = m0 + ty * 8 + i;
        if (gm >= M) continue;
#pragma unroll
        for (int j = 0; j < 8; j++) {
            int gn = n0 + tx * 8 + j;
            if (gn < N) epi(gm, gn, bz, acc[i][j]);
        }
    }
}

// ---------------- LN over 128 per (bt, k, n) -> x_head ----------------
__global__ void k_ln_head(const float* __restrict__ sc, const float* __restrict__ bi) {
    int bt = blockIdx.x, z = blockIdx.y;   // z = k*4 + n_out
    int kk = z >> 2, n = z & 3;
    int ns = g_invp[kk][n];
    int slot = g_slot[kk];
    const float* src = g_z1 + ((size_t)bt * 4 + ns) * DD + slot * DH;
    int tid = threadIdx.x;   // 128 threads
    __shared__ float red[4];
    float v = src[tid];
    float mu = block_sum<4>(v, red) * (1.f / 128.f);
    float d = v - mu;
    float var = block_sum<4>(d * d, red) * (1.f / 128.f);
    g_xh[((size_t)bt * NH + z) * DH + tid] = d * rsqrtf(var + EPSF) * sc[tid] + bi[tid];
}

// ---------------- row softmax over 1024 ----------------
__global__ void k_softmax() {
    __shared__ float red[8];
    size_t base = (((size_t)blockIdx.y << 10) + blockIdx.x) << 10;
    float* p = g_sc + base;
    int tid = threadIdx.x;  // 256
    float v[4];
#pragma unroll
    for (int i = 0; i < 4; i++) v[i] = p[tid + (i << 8)];
    float mx = fmaxf(fmaxf(v[0], v[1]), fmaxf(v[2], v[3]));
    mx = block_max<8>(mx, red);
    float s = 0.f;
#pragma unroll
    for (int i = 0; i < 4; i++) { v[i] = __expf(v[i] - mx); s += v[i]; }
    s = block_sum<8>(s, red);
    float inv = 1.f / s;
#pragma unroll
    for (int i = 0; i < 4; i++) p[tid + (i << 8)] = v[i] * inv;
}

// ---------------- LN over 896 per (bt, n) -> g_hm ----------------
__global__ void k_ln_mixer(const float* __restrict__ sc, const float* __restrict__ bi) {
    __shared__ float red[8];
    size_t row = blockIdx.x;
    const float* src = g_z1 + row * DD;
    float* dst = g_hm + row * DD;
    int tid = threadIdx.x;  // 256
    float v[4];
    float s = 0.f;
#pragma unroll
    for (int i = 0; i < 4; i++) {
        int c = tid + i * 256;
        v[i] = (c < DD) ? src[c] : 0.f;
        s += v[i];
    }
    s = block_sum<8>(s, red);
    float mu = s * (1.f / 896.f);
    float q = 0.f;
#pragma unroll
    for (int i = 0; i < 4; i++) {
        int c = tid + i * 256;
        if (c < DD) { float d = v[i] - mu; q += d * d; }
    }
    q = block_sum<8>(q, red);
    float r = rsqrtf(q * (1.f / 896.f) + EPSF);
#pragma unroll
    for (int i = 0; i < 4; i++) {
        int c = tid + i * 256;
        if (c < DD) dst[c] = (v[i] - mu) * r * sc[c] + bi[c];
    }
}

// ---------------- LN over 3584 per (b,t) -> g_hm ----------------
__global__ void k_ln_dec(const float* __restrict__ sc, const float* __restrict__ bi) {
    __shared__ float red[8];
    size_t row = blockIdx.x;
    const float* src = g_z1 + row * NDD;
    float* dst = g_hm + row * NDD;
    int tid = threadIdx.x;  // 256, 14 elems each (3584 = 14*256)
    float v[14];
    float s = 0.f;
#pragma unroll
    for (int i = 0; i < 14; i++) { v[i] = src[tid + i * 256]; s += v[i]; }
    s = block_sum<8>(s, red);
    float mu = s * (1.f / 3584.f);
    float q = 0.f;
#pragma unroll
    for (int i = 0; i < 14; i++) { float d = v[i] - mu; q += d * d; }
    q = block_sum<8>(q, red);
    float r = rsqrtf(q * (1.f / 3584.f) + EPSF);
#pragma unroll
    for (int i = 0; i < 14; i++) {
        int c = tid + i * 256;
        dst[c] = (v[i] - mu) * r * sc[c] + bi[c];
    }
}

// ---------------- host launch ----------------
static inline float* sym_addr_f(const void* symbol) {
    void* p = nullptr;
    cudaGetSymbolAddress(&p, symbol);
    return (float*)p;
}

extern "C" void kernel_launch(void* const* d_in, const int* in_sizes, int n_in,
                              void* d_out, int out_size) {
    (void)in_sizes; (void)n_in; (void)out_size;
    const float* x          = (const float*)d_in[0];
    const float* enc_base_w = (const float*)d_in[1];
    const float* enc_A_w    = (const float*)d_in[2];
    const float* enc_B      = (const float*)d_in[3];
    const float* enc_beta   = (const float*)d_in[4];
    const float* Wqkv       = (const float*)d_in[5];
    const float* ln_attn_s  = (const float*)d_in[6];
    const float* ln_attn_b  = (const float*)d_in[7];
    const float* ln_mix_s   = (const float*)d_in[8];
    const float* ln_mix_b   = (const float*)d_in[9];
    const float* w1         = (const float*)d_in[10];
    const float* b1         = (const float*)d_in[11];
    const float* w2         = (const float*)d_in[12];
    const float* b2         = (const float*)d_in[13];
    const float* dls        = (const float*)d_in[14];
    const float* dlb        = (const float*)d_in[15];
    const float* down       = (const float*)d_in[16];
    const float* up         = (const float*)d_in[17];
    const int*   phase      = (const int*)d_in[18];
    float* out = (float*)d_out;

    float* p_h   = sym_addr_f(g_h);
    float* p_hm  = sym_addr_f(g_hm);
    float* p_hid = sym_addr_f(g_hidden);
    float* p_xh  = sym_addr_f(g_xh);
    float* p_q   = sym_addr_f(g_q);
    float* p_k   = sym_addr_f(g_k);
    float* p_v   = sym_addr_f(g_v);
    float* p_sc  = sym_addr_f(g_sc);
    float* p_dec = sym_addr_f(g_dec);

    // 0. scalars + phase tables
    k_scalars<<<1, 1>>>(enc_beta, phase);

    // 1. h = x @ enc_A_w.T   (8192 x 64 x 1024, NT)
    gemm<true, false, false><<<dim3(1, 64, 1), 256>>>(
        x, enc_A_w, BTOK, RNK, IOD, IOD, IOD, 0, 0, EpiH{});

    // 2. base = x @ enc_base_w.T, broadcast to 4 slots of z0
    gemm<true, false, false><<<dim3(7, 64, 1), 256>>>(
        x, enc_base_w, BTOK, DD, IOD, IOD, IOD, 0, 0, EpiBase{});

    // 3. z0 += beta * (h @ enc_B)   (8192 x 3584 x 64, NN)
    gemm<false, false, false><<<dim3(28, 64, 1), 256>>>(
        p_h, enc_B, BTOK, NDD, RNK, RNK, NDD, 0, 0, EpiDelta{});

    // 4. LN over slot heads -> x_head
    k_ln_head<<<dim3(BTOK, NH), 128>>>(ln_attn_s, ln_attn_b);

    // 5. qkv per (k,n): batched 12x (8192 x 384 x 128, NN) with head-permute scatter
    gemm<false, false, false><<<dim3(3, 64, 12), 256>>>(
        p_xh, Wqkv, BTOK, 3 * DH, DH, NH * DH, 3 * DH,
        (long)DH, (long)DH * 3 * DH, EpiQKV{});

    // 6. scores = q k^T * scale, causal mask  (96x: 1024x1024x128, NT)
    gemm<true, true, false><<<dim3(8, 8, BB * NH), 256>>>(
        p_q, p_k, TT, TT, DH, DH, DH,
        (long)TT * DH, (long)TT * DH, EpiScore{});

    // 7. softmax rows
    k_softmax<<<dim3(TT, BB * NH), 256>>>();

    // 8. out = P @ V, accumulated into z1 slots (96x: 1024x128x1024, NN, causal k-clip)
    gemm<false, false, true><<<dim3(1, 8, BB * NH), 256>>>(
        p_sc, p_v, TT, DH, TT, TT, DH,
        (long)TT * TT, (long)TT * DH, EpiPV{});

    // 9. mixer LN
    k_ln_mixer<<<dim3(BTOK * N4), 256>>>(ln_mix_s, ln_mix_b);

    // 10. hidden = gelu(hm @ w1.T + b1)   (32768 x 3584 x 896, NT)
    gemm<true, false, false><<<dim3(28, 256, 1), 256>>>(
        p_hm, w1, BTOK * N4, HID, DD, DD, DD, 0, 0, EpiGelu{b1});

    // 11. z2 = z1 + hidden @ w2.T + b2    (32768 x 896 x 3584, NT)
    gemm<true, false, false><<<dim3(7, 256, 1), 256>>>(
        p_hid, w2, BTOK * N4, DD, HID, HID, HID, 0, 0, EpiMix2{b2});

    // 12. decoder LN over 3584
    k_ln_dec<<<dim3(BTOK), 256>>>(dls, dlb);

    // 13. dec = catln @ down.T   (8192 x 64 x 3584, NT)
    gemm<true, false, false><<<dim3(1, 64, 1), 256>>>(
        p_hm, down, BTOK, RNK, NDD, NDD, NDD, 0, 0, EpiDecD{});

    // 14. y = dec @ up.T         (8192 x 1024 x 64, NT)
    gemm<true, false, false><<<dim3(8, 64, 1), 256>>>(
        p_dec, up, BTOK, IOD, RNK, RNK, RNK, 0, 0, EpiOut{out});
}

// round 2
// speedup vs baseline: 2.5104x; 2.5104x over previous
#include <cuda_runtime.h>
#include <math.h>
#include <stdint.h>

// ---------------- problem constants ----------------
#define BB   8
#define TT   1024
#define BTOK (BB*TT)          // 8192
#define N4   4
#define K3   3
#define DH   128
#define DD   896              // S*DH
#define NDD  3584             // N*D
#define HID  3584             // 4*D
#define IOD  1024
#define RNK  64
#define NH   12               // N*K heads
#define EPSF 1e-5f

// ---------------- device scratch ----------------
__device__ float g_beta;
__device__ int   g_slot[3];
__device__ int   g_invp[3][4];

__device__ __align__(16) float g_h[BTOK*RNK];
__device__ __align__(16) float g_z1[(size_t)BTOK*NDD];
__device__ __align__(16) float g_hm[(size_t)BTOK*NDD];
__device__ __align__(16) float g_hidden[(size_t)BTOK*4*HID];
__device__ __align__(16) float g_xh[(size_t)BTOK*NH*DH];
__device__ __align__(16) float g_q[(size_t)BB*NH*TT*DH];
__device__ __align__(16) float g_k[(size_t)BB*NH*TT*DH];
__device__ __align__(16) float g_v[(size_t)BB*NH*TT*DH];
__device__ __align__(16) float g_sc[(size_t)BB*NH*TT*TT];
__device__ __align__(16) float g_dec[BTOK*RNK];

// ---------------- scalar / table prologue ----------------
__global__ void k_scalars(const float* beta, const int* phase) {
    g_beta = *beta;
    int ph = *phase;
    int off = 0;
    const int sc[3] = {1, 2, 4};
    for (int k = 0; k < 3; k++) {
        int s = sc[k];
        int j = ph % s;
        g_slot[k] = off + j;
        off += s;
        int alpha = 4 / s;
        for (int i = 0; i < 4; i++) {
            int p = (i + alpha * j) & 3;
            g_invp[k][p] = i;
        }
    }
}

// ---------------- block reductions ----------------
template<int W>
__device__ __forceinline__ float block_sum(float x, float* red) {
#pragma unroll
    for (int o = 16; o > 0; o >>= 1) x += __shfl_xor_sync(0xffffffffu, x, o);
    __syncthreads();
    if ((threadIdx.x & 31) == 0) red[threadIdx.x >> 5] = x;
    __syncthreads();
    float s = 0.f;
#pragma unroll
    for (int i = 0; i < W; i++) s += red[i];
    return s;
}
template<int W>
__device__ __forceinline__ float block_max(float x, float* red) {
#pragma unroll
    for (int o = 16; o > 0; o >>= 1) x = fmaxf(x, __shfl_xor_sync(0xffffffffu, x, o));
    __syncthreads();
    if ((threadIdx.x & 31) == 0) red[threadIdx.x >> 5] = x;
    __syncthreads();
    float s = -1e30f;
#pragma unroll
    for (int i = 0; i < W; i++) s = fmaxf(s, red[i]);
    return s;
}

// ---------------- epilogue functors ----------------
struct EpiH {
    __device__ void operator()(int m, int n, int, float v) const { g_h[m*RNK + n] = v; }
};
struct EpiBase {
    __device__ void operator()(int m, int n, int, float v) const {
        size_t base = (size_t)m * NDD + n;
        g_z1[base] = v; g_z1[base + DD] = v; g_z1[base + 2*DD] = v; g_z1[base + 3*DD] = v;
    }
};
struct EpiDelta {
    __device__ void operator()(int m, int n, int, float v) const {
        g_z1[(size_t)m * NDD + n] += g_beta * v;
    }
};
struct EpiQKV {
    __device__ void operator()(int m, int n, int bz, float v) const {
        int b = m >> 10, t = m & 1023;
        int kk = bz >> 2, ns = bz & 3;
        int h = g_invp[kk][ns] * 3 + kk;
        float* dst; int e = n;
        if (e < DH)            { dst = g_q; }
        else if (e < 2*DH)     { dst = g_k; e -= DH; }
        else                   { dst = g_v; e -= 2*DH; }
        dst[(((size_t)b * NH + h) * TT + t) * DH + e] = v;
    }
};
struct EpiScore {
    __device__ void operator()(int m, int n, int bz, float v) const {
        g_sc[((size_t)bz * TT + m) * TT + n] =
            (n <= m) ? v * 0.088388347648318447f : -1e9f;
    }
};
struct EpiPV {
    __device__ void operator()(int m, int n, int bz, float v) const {
        int b = bz / NH, h = bz % NH;
        int kk = h % 3, nn = h / 3;
        int slot = g_slot[kk];
        g_z1[(((size_t)(b * TT + m)) * N4 + nn) * DD + slot * DH + n] += v;
    }
};
struct EpiGelu {
    const float* b1;
    __device__ void operator()(int m, int n, int, float v) const {
        float u = v + b1[n];
        g_hidden[(size_t)m * HID + n] = 0.5f * u * (1.f + erff(u * 0.70710678118654752f));
    }
};
struct EpiMix2 {
    const float* b2;
    __device__ void operator()(int m, int n, int, float v) const {
        g_z1[(size_t)m * DD + n] += v + b2[n];
    }
};
struct EpiDecD {
    __device__ void operator()(int m, int n, int, float v) const { g_dec[m*RNK + n] = v; }
};
struct EpiOut {
    float* out;
    __device__ void operator()(int m, int n, int, float v) const { out[(size_t)m * IOD + n] = v; }
};

// ================= tf32 tensor-core GEMM =================
__device__ __forceinline__ uint32_t f2tf(float f) {
    uint32_t u; asm("cvt.rna.tf32.f32 %0, %1;" : "=r"(u) : "f"(f)); return u;
}
__device__ __forceinline__ void mma_tf32(float* c, const uint32_t* a, const uint32_t* b) {
    asm volatile("mma.sync.aligned.m16n8k8.row.col.f32.tf32.tf32.f32 "
        "{%0,%1,%2,%3},{%4,%5,%6,%7},{%8,%9},{%0,%1,%2,%3};"
        : "+f"(c[0]), "+f"(c[1]), "+f"(c[2]), "+f"(c[3])
        : "r"(a[0]), "r"(a[1]), "r"(a[2]), "r"(a[3]), "r"(b[0]), "r"(b[1]));
}

// Block tile 128x128, BK=32, 8 warps (2m x 4n), warp tile 64x32.
// A row-major (M x K). BT_=true: B row-major (N x K). BT_=false: B (K x N).
// Requires: M % 128 == 0, Kd % 32 == 0, lda/ldb % 4 == 0.
template<bool BT_, bool CSKIP, bool CKLIM, class Epi>
__global__ void __launch_bounds__(256)
tgemm(const float* __restrict__ A, const float* __restrict__ B,
      int M, int N, int Kd, int lda, int ldb, long sA, long sB, Epi epi)
{
    const int bz = blockIdx.z;
    A += (size_t)bz * sA;
    B += (size_t)bz * sB;
    const int m0 = blockIdx.y * 128, n0 = blockIdx.x * 128;
    const int tid = threadIdx.x;
    const int lane = tid & 31, wid = tid >> 5;
    const int wm = (wid & 1) * 64, wn = (wid >> 1) * 32;

    __shared__ uint32_t As[128][36];
    __shared__ uint32_t Bs[128][36];

    float c[16][4];
#pragma unroll
    for (int i = 0; i < 16; i++)
#pragma unroll
        for (int j = 0; j < 4; j++) c[i][j] = 0.f;

    if (!(CSKIP && n0 >= m0 + 128)) {
        int kEnd = CKLIM ? ((Kd < m0 + 128) ? Kd : (m0 + 128)) : Kd;
        for (int k0 = 0; k0 < kEnd; k0 += 32) {
            // ---- load A tile (128 x 32), float4 along k ----
#pragma unroll
            for (int i = 0; i < 4; i++) {
                int idx = tid + i * 256;       // quad index 0..1023
                int r = idx >> 3, q = (idx & 7) * 4;
                float4 f = *(const float4*)(A + (size_t)(m0 + r) * lda + k0 + q);
                uint4 u; u.x = f2tf(f.x); u.y = f2tf(f.y); u.z = f2tf(f.z); u.w = f2tf(f.w);
                *(uint4*)&As[r][q] = u;
            }
            // ---- load B tile into Bs[n][k] ----
            if (BT_) {
#pragma unroll
                for (int i = 0; i < 4; i++) {
                    int idx = tid + i * 256;
                    int r = idx >> 3, q = (idx & 7) * 4;
                    int gn = n0 + r;
                    uint4 u;
                    if (gn < N) {
                        float4 f = *(const float4*)(B + (size_t)gn * ldb + k0 + q);
                        u.x = f2tf(f.x); u.y = f2tf(f.y); u.z = f2tf(f.z); u.w = f2tf(f.w);
                    } else { u.x = u.y = u.z = u.w = 0u; }
                    *(uint4*)&Bs[r][q] = u;
                }
            } else {
                int n = tid & 127, kq = (tid >> 7) * 16;
                int gn = n0 + n;
#pragma unroll
                for (int j = 0; j < 4; j++) {
                    int kb = kq + j * 4;
                    uint4 u;
                    if (gn < N) {
                        const float* bp = B + (size_t)(k0 + kb) * ldb + gn;
                        u.x = f2tf(bp[0]);
                        u.y = f2tf(bp[(size_t)ldb]);
                        u.z = f2tf(bp[(size_t)2 * ldb]);
                        u.w = f2tf(bp[(size_t)3 * ldb]);
                    } else { u.x = u.y = u.z = u.w = 0u; }
                    *(uint4*)&Bs[n][kb] = u;
                }
            }
            __syncthreads();
            // ---- compute 4 k8-steps ----
#pragma unroll
            for (int ks = 0; ks < 4; ks++) {
                int kk = ks * 8;
                uint32_t a[4][4], b[4][2];
                int ar = lane >> 2, ac = kk + (lane & 3);
#pragma unroll
                for (int mt = 0; mt < 4; mt++) {
                    int row = wm + mt * 16 + ar;
                    a[mt][0] = As[row][ac];
                    a[mt][1] = As[row + 8][ac];
                    a[mt][2] = As[row][ac + 4];
                    a[mt][3] = As[row + 8][ac + 4];
                }
#pragma unroll
                for (int nt = 0; nt < 4; nt++) {
                    int col = wn + nt * 8 + ar;
                    b[nt][0] = Bs[col][ac];
                    b[nt][1] = Bs[col][ac + 4];
                }
#pragma unroll
                for (int mt = 0; mt < 4; mt++)
#pragma unroll
                    for (int nt = 0; nt < 4; nt++)
                        mma_tf32(c[mt * 4 + nt], a[mt], b[nt]);
            }
            __syncthreads();
        }
    }
    // ---- epilogue ----
#pragma unroll
    for (int mt = 0; mt < 4; mt++)
#pragma unroll
        for (int nt = 0; nt < 4; nt++)
#pragma unroll
            for (int r = 0; r < 4; r++) {
                int gm = m0 + wm + mt * 16 + (lane >> 2) + (r >> 1) * 8;
                int gn = n0 + wn + nt * 8 + (lane & 3) * 2 + (r & 1);
                if (gn < N) epi(gm, gn, bz, c[mt * 4 + nt][r]);
            }
}

// ---------------- fp32 tiled GEMM (kept for small/precision-critical GEMMs) ----------------
template<bool BT_, class Epi>
__global__ void __launch_bounds__(256)
gemm(const float* __restrict__ A, const float* __restrict__ B,
     int M, int N, int Kd, int lda, int ldb, long sA, long sB, Epi epi)
{
    const int bz = blockIdx.z;
    A += (size_t)bz * sA;
    B += (size_t)bz * sB;
    const int m0 = blockIdx.y * 128, n0 = blockIdx.x * 128;
    const int tid = threadIdx.x, tx = tid & 15, ty = tid >> 4;

    __shared__ float As[16][132];
    __shared__ float Bs[16][132];

    float acc[8][8];
#pragma unroll
    for (int i = 0; i < 8; i++)
#pragma unroll
        for (int j = 0; j < 8; j++) acc[i][j] = 0.f;

    for (int k0 = 0; k0 < Kd; k0 += 16) {
#pragma unroll
        for (int i = 0; i < 8; i++) {
            int idx = i * 256 + tid;
            int mm = idx >> 4, kk = idx & 15;
            int gm = m0 + mm, gk = k0 + kk;
            As[kk][mm] = (gm < M && gk < Kd) ? A[(size_t)gm * lda + gk] : 0.f;
        }
        if (BT_) {
#pragma unroll
            for (int i = 0; i < 8; i++) {
                int idx = i * 256 + tid;
                int nn = idx >> 4, kk = idx & 15;
                int gn = n0 + nn, gk = k0 + kk;
                Bs[kk][nn] = (gn < N && gk < Kd) ? B[(size_t)gn * ldb + gk] : 0.f;
            }
        } else {
#pragma unroll
            for (int i = 0; i < 8; i++) {
                int idx = i * 256 + tid;
                int nn = idx & 127, kk = idx >> 7;
                int gn = n0 + nn, gk = k0 + kk;
                Bs[kk][nn] = (gn < N && gk < Kd) ? B[(size_t)gk * ldb + gn] : 0.f;
            }
        }
        __syncthreads();
#pragma unroll
        for (int kk = 0; kk < 16; kk++) {
            float a[8], b[8];
#pragma unroll
            for (int i = 0; i < 8; i++) a[i] = As[kk][ty * 8 + i];
#pragma unroll
            for (int j = 0; j < 8; j++) b[j] = Bs[kk][tx * 8 + j];
#pragma unroll
            for (int i = 0; i < 8; i++)
#pragma unroll
                for (int j = 0; j < 8; j++) acc[i][j] = fmaf(a[i], b[j], acc[i][j]);
        }
        __syncthreads();
    }
#pragma unroll
    for (int i = 0; i < 8; i++) {
        int gm = m0 + ty * 8 + i;
        if (gm >= M) continue;
#pragma unroll
        for (int j = 0; j < 8; j++) {
            int gn = n0 + tx * 8 + j;
            if (gn < N) epi(gm, gn, bz, acc[i][j]);
        }
    }
}

// ---------------- LN over 128 per (bt, k, n) -> x_head ----------------
__global__ void k_ln_head(const float* __restrict__ sc, const float* __restrict__ bi) {
    int bt = blockIdx.x, z = blockIdx.y;
    int kk = z >> 2, n = z & 3;
    int ns = g_invp[kk][n];
    int slot = g_slot[kk];
    const float* src = g_z1 + ((size_t)bt * 4 + ns) * DD + slot * DH;
    int tid = threadIdx.x;
    __shared__ float red[4];
    float v = src[tid];
    float mu = block_sum<4>(v, red) * (1.f / 128.f);
    float d = v - mu;
    float var = block_sum<4>(d * d, red) * (1.f / 128.f);
    g_xh[((size_t)bt * NH + z) * DH + tid] = d * rsqrtf(var + EPSF) * sc[tid] + bi[tid];
}

// ---------------- row softmax over 1024 ----------------
__global__ void k_softmax() {
    __shared__ float red[8];
    size_t base = (((size_t)blockIdx.y << 10) + blockIdx.x) << 10;
    float* p = g_sc + base;
    int tid = threadIdx.x;
    float v[4];
#pragma unroll
    for (int i = 0; i < 4; i++) v[i] = p[tid + (i << 8)];
    float mx = fmaxf(fmaxf(v[0], v[1]), fmaxf(v[2], v[3]));
    mx = block_max<8>(mx, red);
    float s = 0.f;
#pragma unroll
    for (int i = 0; i < 4; i++) { v[i] = __expf(v[i] - mx); s += v[i]; }
    s = block_sum<8>(s, red);
    float inv = 1.f / s;
#pragma unroll
    for (int i = 0; i < 4; i++) p[tid + (i << 8)] = v[i] * inv;
}

// ---------------- LN over 896 ----------------
__global__ void k_ln_mixer(const float* __restrict__ sc, const float* __restrict__ bi) {
    __shared__ float red[8];
    size_t row = blockIdx.x;
    const float* src = g_z1 + row * DD;
    float* dst = g_hm + row * DD;
    int tid = threadIdx.x;
    float v[4];
    float s = 0.f;
#pragma unroll
    for (int i = 0; i < 4; i++) {
        int c = tid + i * 256;
        v[i] = (c < DD) ? src[c] : 0.f;
        s += v[i];
    }
    s = block_sum<8>(s, red);
    float mu = s * (1.f / 896.f);
    float q = 0.f;
#pragma unroll
    for (int i = 0; i < 4; i++) {
        int c = tid + i * 256;
        if (c < DD) { float d = v[i] - mu; q += d * d; }
    }
    q = block_sum<8>(q, red);
    float r = rsqrtf(q * (1.f / 896.f) + EPSF);
#pragma unroll
    for (int i = 0; i < 4; i++) {
        int c = tid + i * 256;
        if (c < DD) dst[c] = (v[i] - mu) * r * sc[c] + bi[c];
    }
}

// ---------------- LN over 3584 ----------------
__global__ void k_ln_dec(const float* __restrict__ sc, const float* __restrict__ bi) {
    __shared__ float red[8];
    size_t row = blockIdx.x;
    const float* src = g_z1 + row * NDD;
    float* dst = g_hm + row * NDD;
    int tid = threadIdx.x;
    float v[14];
    float s = 0.f;
#pragma unroll
    for (int i = 0; i < 14; i++) { v[i] = src[tid + i * 256]; s += v[i]; }
    s = block_sum<8>(s, red);
    float mu = s * (1.f / 3584.f);
    float q = 0.f;
#pragma unroll
    for (int i = 0; i < 14; i++) { float d = v[i] - mu; q += d * d; }
    q = block_sum<8>(q, red);
    float r = rsqrtf(q * (1.f / 3584.f) + EPSF);
#pragma unroll
    for (int i = 0; i < 14; i++) {
        int c = tid + i * 256;
        dst[c] = (v[i] - mu) * r * sc[c] + bi[c];
    }
}

// ---------------- host launch ----------------
static inline float* sym_addr_f(const void* symbol) {
    void* p = nullptr;
    cudaGetSymbolAddress(&p, symbol);
    return (float*)p;
}

extern "C" void kernel_launch(void* const* d_in, const int* in_sizes, int n_in,
                              void* d_out, int out_size) {
    (void)in_sizes; (void)n_in; (void)out_size;
    const float* x          = (const float*)d_in[0];
    const float* enc_base_w = (const float*)d_in[1];
    const float* enc_A_w    = (const float*)d_in[2];
    const float* enc_B      = (const float*)d_in[3];
    const float* enc_beta   = (const float*)d_in[4];
    const float* Wqkv       = (const float*)d_in[5];
    const float* ln_attn_s  = (const float*)d_in[6];
    const float* ln_attn_b  = (const float*)d_in[7];
    const float* ln_mix_s   = (const float*)d_in[8];
    const float* ln_mix_b   = (const float*)d_in[9];
    const float* w1         = (const float*)d_in[10];
    const float* b1         = (const float*)d_in[11];
    const float* w2         = (const float*)d_in[12];
    const float* b2         = (const float*)d_in[13];
    const float* dls        = (const float*)d_in[14];
    const float* dlb        = (const float*)d_in[15];
    const float* down       = (const float*)d_in[16];
    const float* up         = (const float*)d_in[17];
    const int*   phase      = (const int*)d_in[18];
    float* out = (float*)d_out;

    float* p_h   = sym_addr_f(g_h);
    float* p_hm  = sym_addr_f(g_hm);
    float* p_hid = sym_addr_f(g_hidden);
    float* p_xh  = sym_addr_f(g_xh);
    float* p_q   = sym_addr_f(g_q);
    float* p_k   = sym_addr_f(g_k);
    float* p_v   = sym_addr_f(g_v);
    float* p_sc  = sym_addr_f(g_sc);
    float* p_dec = sym_addr_f(g_dec);

    // 0. scalars + phase tables
    k_scalars<<<1, 1>>>(enc_beta, phase);

    // 1. h = x @ enc_A_w.T  (fp32; feeds beta-scaled delta, keep exact)
    gemm<true><<<dim3(1, 64, 1), 256>>>(
        x, enc_A_w, BTOK, RNK, IOD, IOD, IOD, 0, 0, EpiH{});

    // 2. base = x @ enc_base_w.T -> broadcast to z0  (tf32 NT)
    tgemm<true, false, false><<<dim3(7, 64, 1), 256>>>(
        x, enc_base_w, BTOK, DD, IOD, IOD, IOD, 0, 0, EpiBase{});

    // 3. z0 += beta * (h @ enc_B)  (tf32 NN)
    tgemm<false, false, false><<<dim3(28, 64, 1), 256>>>(
        p_h, enc_B, BTOK, NDD, RNK, RNK, NDD, 0, 0, EpiDelta{});

    // 4. LN over slot heads -> x_head
    k_ln_head<<<dim3(BTOK, NH), 128>>>(ln_attn_s, ln_attn_b);

    // 5. qkv (tf32 NN, batched 12)
    tgemm<false, false, false><<<dim3(3, 64, 12), 256>>>(
        p_xh, Wqkv, BTOK, 3 * DH, DH, NH * DH, 3 * DH,
        (long)DH, (long)DH * 3 * DH, EpiQKV{});

    // 6. scores (tf32 NT, causal skip)
    tgemm<true, true, false><<<dim3(8, 8, BB * NH), 256>>>(
        p_q, p_k, TT, TT, DH, DH, DH,
        (long)TT * DH, (long)TT * DH, EpiScore{});

    // 7. softmax
    k_softmax<<<dim3(TT, BB * NH), 256>>>();

    // 8. out = P @ V (tf32 NN, causal k-clip), accumulate into z1
    tgemm<false, false, true><<<dim3(1, 8, BB * NH), 256>>>(
        p_sc, p_v, TT, DH, TT, TT, DH,
        (long)TT * TT, (long)TT * DH, EpiPV{});

    // 9. mixer LN
    k_ln_mixer<<<dim3(BTOK * N4), 256>>>(ln_mix_s, ln_mix_b);

    // 10. hidden = gelu(hm @ w1.T + b1)  (tf32 NT)
    tgemm<true, false, false><<<dim3(28, 256, 1), 256>>>(
        p_hm, w1, BTOK * N4, HID, DD, DD, DD, 0, 0, EpiGelu{b1});

    // 11. z2 = z1 + hidden @ w2.T + b2  (tf32 NT)
    tgemm<true, false, false><<<dim3(7, 256, 1), 256>>>(
        p_hid, w2, BTOK * N4, DD, HID, HID, HID, 0, 0, EpiMix2{b2});

    // 12. decoder LN
    k_ln_dec<<<dim3(BTOK), 256>>>(dls, dlb);

    // 13. dec = catln @ down.T  (fp32, precision-critical final path)
    gemm<true><<<dim3(1, 64, 1), 256>>>(
        p_hm, down, BTOK, RNK, NDD, NDD, NDD, 0, 0, EpiDecD{});

    // 14. y = dec @ up.T  (fp32)
    gemm<true><<<dim3(8, 64, 1), 256>>>(
        p_dec, up, BTOK, IOD, RNK, RNK, RNK, 0, 0, EpiOut{out});
}

// round 3
// speedup vs baseline: 3.5148x; 1.4001x over previous
#include <cuda_runtime.h>
#include <math.h>
#include <stdint.h>

// ---------------- problem constants ----------------
#define BB   8
#define TT   1024
#define BTOK (BB*TT)          // 8192
#define N4   4
#define K3   3
#define DH   128
#define DD   896              // S*DH
#define NDD  3584             // N*D
#define HID  3584             // 4*D
#define IOD  1024
#define RNK  64
#define NH   12               // N*K heads
#define EPSF 1e-5f

// ---------------- device scratch ----------------
__device__ float g_beta;
__device__ int   g_slot[3];
__device__ int   g_invp[3][4];

__device__ __align__(16) float g_h[BTOK*RNK];
__device__ __align__(16) float g_z1[(size_t)BTOK*NDD];
__device__ __align__(16) float g_hm[(size_t)BTOK*NDD];
__device__ __align__(16) float g_hidden[(size_t)BTOK*4*HID];
__device__ __align__(16) float g_xh[(size_t)BTOK*NH*DH];
__device__ __align__(16) float g_q[(size_t)BB*NH*TT*DH];
__device__ __align__(16) float g_k[(size_t)BB*NH*TT*DH];
__device__ __align__(16) float g_v[(size_t)BB*NH*TT*DH];
__device__ __align__(16) float g_sc[(size_t)BB*NH*TT*TT];
__device__ __align__(16) float g_dec[BTOK*RNK];

// ---------------- scalar / table prologue ----------------
__global__ void k_scalars(const float* beta, const int* phase) {
    g_beta = *beta;
    int ph = *phase;
    int off = 0;
    const int sc[3] = {1, 2, 4};
    for (int k = 0; k < 3; k++) {
        int s = sc[k];
        int j = ph % s;
        g_slot[k] = off + j;
        off += s;
        int alpha = 4 / s;
        for (int i = 0; i < 4; i++) {
            int p = (i + alpha * j) & 3;
            g_invp[k][p] = i;
        }
    }
}

// ---------------- block reductions ----------------
template<int W>
__device__ __forceinline__ float block_sum(float x, float* red) {
#pragma unroll
    for (int o = 16; o > 0; o >>= 1) x += __shfl_xor_sync(0xffffffffu, x, o);
    __syncthreads();
    if ((threadIdx.x & 31) == 0) red[threadIdx.x >> 5] = x;
    __syncthreads();
    float s = 0.f;
#pragma unroll
    for (int i = 0; i < W; i++) s += red[i];
    return s;
}
template<int W>
__device__ __forceinline__ float block_max(float x, float* red) {
#pragma unroll
    for (int o = 16; o > 0; o >>= 1) x = fmaxf(x, __shfl_xor_sync(0xffffffffu, x, o));
    __syncthreads();
    if ((threadIdx.x & 31) == 0) red[threadIdx.x >> 5] = x;
    __syncthreads();
    float s = -1e30f;
#pragma unroll
    for (int i = 0; i < W; i++) s = fmaxf(s, red[i]);
    return s;
}

// ---------------- epilogue functors ----------------
struct EpiH {
    __device__ void operator()(int m, int n, int, float v) const { g_h[m*RNK + n] = v; }
};
struct EpiBase {
    __device__ void operator()(int m, int n, int, float v) const {
        size_t base = (size_t)m * NDD + n;
        g_z1[base] = v; g_z1[base + DD] = v; g_z1[base + 2*DD] = v; g_z1[base + 3*DD] = v;
    }
};
struct EpiDelta {
    __device__ void operator()(int m, int n, int, float v) const {
        g_z1[(size_t)m * NDD + n] += g_beta * v;
    }
};
struct EpiQKV {
    __device__ void operator()(int m, int n, int bz, float v) const {
        int b = m >> 10, t = m & 1023;
        int kk = bz >> 2, ns = bz & 3;
        int h = g_invp[kk][ns] * 3 + kk;
        float* dst; int e = n;
        if (e < DH)            { dst = g_q; }
        else if (e < 2*DH)     { dst = g_k; e -= DH; }
        else                   { dst = g_v; e -= 2*DH; }
        dst[(((size_t)b * NH + h) * TT + t) * DH + e] = v;
    }
};
struct EpiScore {
    __device__ void operator()(int m, int n, int bz, float v) const {
        g_sc[((size_t)bz * TT + m) * TT + n] =
            (n <= m) ? v * 0.088388347648318447f : -1e9f;
    }
};
struct EpiPV {
    __device__ void operator()(int m, int n, int bz, float v) const {
        int b = bz / NH, h = bz % NH;
        int kk = h % 3, nn = h / 3;
        int slot = g_slot[kk];
        g_z1[(((size_t)(b * TT + m)) * N4 + nn) * DD + slot * DH + n] += v;
    }
};
struct EpiGelu {
    const float* b1;
    __device__ void operator()(int m, int n, int, float v) const {
        float u = v + b1[n];
        g_hidden[(size_t)m * HID + n] = 0.5f * u * (1.f + erff(u * 0.70710678118654752f));
    }
};
struct EpiMix2 {
    const float* b2;
    __device__ void operator()(int m, int n, int, float v) const {
        g_z1[(size_t)m * DD + n] += v + b2[n];
    }
};
struct EpiDecD {
    __device__ void operator()(int m, int n, int, float v) const { g_dec[m*RNK + n] = v; }
};
struct EpiOut {
    float* out;
    __device__ void operator()(int m, int n, int, float v) const { out[(size_t)m * IOD + n] = v; }
};

// ================= tf32 tensor-core GEMM =================
__device__ __forceinline__ uint32_t f2tf(float f) {
    uint32_t u; asm("cvt.rna.tf32.f32 %0, %1;" : "=r"(u) : "f"(f)); return u;
}
__device__ __forceinline__ void mma_tf32(float* c, const uint32_t* a, const uint32_t* b) {
    asm volatile("mma.sync.aligned.m16n8k8.row.col.f32.tf32.tf32.f32 "
        "{%0,%1,%2,%3},{%4,%5,%6,%7},{%8,%9},{%0,%1,%2,%3};"
        : "+f"(c[0]), "+f"(c[1]), "+f"(c[2]), "+f"(c[3])
        : "r"(a[0]), "r"(a[1]), "r"(a[2]), "r"(a[3]), "r"(b[0]), "r"(b[1]));
}

// Block tile 128x128, BK=32, 8 warps (2m x 4n), warp tile 64x32.
// Software-pipelined: next k-tile's global loads are issued before compute.
// A row-major (M x K). BT_=true: B row-major (N x K). BT_=false: B (K x N).
// Requires: M % 128 == 0, Kd % 32 == 0, lda/ldb % 4 == 0.
template<bool BT_, bool CSKIP, bool CKLIM, class Epi>
__global__ void __launch_bounds__(256, 2)
tgemm(const float* __restrict__ A, const float* __restrict__ B,
      int M, int N, int Kd, int lda, int ldb, long sA, long sB, Epi epi)
{
    const int bz = blockIdx.z;
    A += (size_t)bz * sA;
    B += (size_t)bz * sB;
    const int m0 = blockIdx.y * 128, n0 = blockIdx.x * 128;
    const int tid = threadIdx.x;
    const int lane = tid & 31, wid = tid >> 5;
    const int wm = (wid & 1) * 64, wn = (wid >> 1) * 32;

    __shared__ uint32_t As[128][36];
    __shared__ uint32_t Bs[128][36];

    float c[16][4];
#pragma unroll
    for (int i = 0; i < 16; i++)
#pragma unroll
        for (int j = 0; j < 4; j++) c[i][j] = 0.f;

    if (!(CSKIP && n0 >= m0 + 128)) {
        int kEnd = CKLIM ? ((Kd < m0 + 128) ? Kd : (m0 + 128)) : Kd;

        // A-load geometry: thread covers (row, 4k) quad
        const int arw = tid >> 3, aq = (tid & 7) * 4;
        // B NN geometry
        const int bnn = tid & 127, bkq = (tid >> 7) * 16;
        const int gnn = n0 + bnn;

        float4 ra[4];
        float  rb[16];

        // ---- prologue: load tile k0=0 into registers ----
        {
#pragma unroll
            for (int i = 0; i < 4; i++)
                ra[i] = *(const float4*)(A + (size_t)(m0 + arw + i * 32) * lda + aq);
            if (BT_) {
#pragma unroll
                for (int i = 0; i < 4; i++) {
                    int gn = n0 + arw + i * 32;
                    float4 f = (gn < N) ? *(const float4*)(B + (size_t)gn * ldb + aq)
                                        : make_float4(0.f, 0.f, 0.f, 0.f);
                    rb[i*4+0] = f.x; rb[i*4+1] = f.y; rb[i*4+2] = f.z; rb[i*4+3] = f.w;
                }
            } else {
#pragma unroll
                for (int j = 0; j < 16; j++) {
                    int gk = bkq + j;
                    rb[j] = (gnn < N) ? B[(size_t)gk * ldb + gnn] : 0.f;
                }
            }
        }

        for (int k0 = 0; k0 < kEnd; k0 += 32) {
            // ---- store regs -> smem (with tf32 convert) ----
#pragma unroll
            for (int i = 0; i < 4; i++) {
                uint4 u;
                u.x = f2tf(ra[i].x); u.y = f2tf(ra[i].y);
                u.z = f2tf(ra[i].z); u.w = f2tf(ra[i].w);
                *(uint4*)&As[arw + i * 32][aq] = u;
            }
            if (BT_) {
#pragma unroll
                for (int i = 0; i < 4; i++) {
                    uint4 u;
                    u.x = f2tf(rb[i*4+0]); u.y = f2tf(rb[i*4+1]);
                    u.z = f2tf(rb[i*4+2]); u.w = f2tf(rb[i*4+3]);
                    *(uint4*)&Bs[arw + i * 32][aq] = u;
                }
            } else {
#pragma unroll
                for (int j = 0; j < 4; j++) {
                    uint4 u;
                    u.x = f2tf(rb[j*4+0]); u.y = f2tf(rb[j*4+1]);
                    u.z = f2tf(rb[j*4+2]); u.w = f2tf(rb[j*4+3]);
                    *(uint4*)&Bs[bnn][bkq + j * 4] = u;
                }
            }
            __syncthreads();

            // ---- prefetch next tile (LDGs overlap the MMA block below) ----
            if (k0 + 32 < kEnd) {
                int kn = k0 + 32;
#pragma unroll
                for (int i = 0; i < 4; i++)
                    ra[i] = *(const float4*)(A + (size_t)(m0 + arw + i * 32) * lda + kn + aq);
                if (BT_) {
#pragma unroll
                    for (int i = 0; i < 4; i++) {
                        int gn = n0 + arw + i * 32;
                        float4 f = (gn < N) ? *(const float4*)(B + (size_t)gn * ldb + kn + aq)
                                            : make_float4(0.f, 0.f, 0.f, 0.f);
                        rb[i*4+0] = f.x; rb[i*4+1] = f.y; rb[i*4+2] = f.z; rb[i*4+3] = f.w;
                    }
                } else {
#pragma unroll
                    for (int j = 0; j < 16; j++) {
                        int gk = kn + bkq + j;
                        rb[j] = (gnn < N) ? B[(size_t)gk * ldb + gnn] : 0.f;
                    }
                }
            }

            // ---- compute 4 k8-steps ----
#pragma unroll
            for (int ks = 0; ks < 4; ks++) {
                int kk = ks * 8;
                uint32_t a[4][4], b[4][2];
                int ar = lane >> 2, ac = kk + (lane & 3);
#pragma unroll
                for (int mt = 0; mt < 4; mt++) {
                    int row = wm + mt * 16 + ar;
                    a[mt][0] = As[row][ac];
                    a[mt][1] = As[row + 8][ac];
                    a[mt][2] = As[row][ac + 4];
                    a[mt][3] = As[row + 8][ac + 4];
                }
#pragma unroll
                for (int nt = 0; nt < 4; nt++) {
                    int col = wn + nt * 8 + ar;
                    b[nt][0] = Bs[col][ac];
                    b[nt][1] = Bs[col][ac + 4];
                }
#pragma unroll
                for (int mt = 0; mt < 4; mt++)
#pragma unroll
                    for (int nt = 0; nt < 4; nt++)
                        mma_tf32(c[mt * 4 + nt], a[mt], b[nt]);
            }
            __syncthreads();
        }
    }
    // ---- epilogue ----
#pragma unroll
    for (int mt = 0; mt < 4; mt++)
#pragma unroll
        for (int nt = 0; nt < 4; nt++)
#pragma unroll
            for (int r = 0; r < 4; r++) {
                int gm = m0 + wm + mt * 16 + (lane >> 2) + (r >> 1) * 8;
                int gn = n0 + wn + nt * 8 + (lane & 3) * 2 + (r & 1);
                if (gn < N) epi(gm, gn, bz, c[mt * 4 + nt][r]);
            }
}

// ---------------- fp32 tiled GEMM (small/precision-critical GEMMs) ----------------
template<bool BT_, class Epi>
__global__ void __launch_bounds__(256, 2)
gemm(const float* __restrict__ A, const float* __restrict__ B,
     int M, int N, int Kd, int lda, int ldb, long sA, long sB, Epi epi)
{
    const int bz = blockIdx.z;
    A += (size_t)bz * sA;
    B += (size_t)bz * sB;
    const int m0 = blockIdx.y * 128, n0 = blockIdx.x * 128;
    const int tid = threadIdx.x, tx = tid & 15, ty = tid >> 4;

    __shared__ float As[16][132];
    __shared__ float Bs[16][132];

    float acc[8][8];
#pragma unroll
    for (int i = 0; i < 8; i++)
#pragma unroll
        for (int j = 0; j < 8; j++) acc[i][j] = 0.f;

    for (int k0 = 0; k0 < Kd; k0 += 16) {
#pragma unroll
        for (int i = 0; i < 8; i++) {
            int idx = i * 256 + tid;
            int mm = idx >> 4, kk = idx & 15;
            int gm = m0 + mm, gk = k0 + kk;
            As[kk][mm] = (gm < M && gk < Kd) ? A[(size_t)gm * lda + gk] : 0.f;
        }
        if (BT_) {
#pragma unroll
            for (int i = 0; i < 8; i++) {
                int idx = i * 256 + tid;
                int nn = idx >> 4, kk = idx & 15;
                int gn = n0 + nn, gk = k0 + kk;
                Bs[kk][nn] = (gn < N && gk < Kd) ? B[(size_t)gn * ldb + gk] : 0.f;
            }
        } else {
#pragma unroll
            for (int i = 0; i < 8; i++) {
                int idx = i * 256 + tid;
                int nn = idx & 127, kk = idx >> 7;
                int gn = n0 + nn, gk = k0 + kk;
                Bs[kk][nn] = (gn < N && gk < Kd) ? B[(size_t)gk * ldb + gn] : 0.f;
            }
        }
        __syncthreads();
#pragma unroll
        for (int kk = 0; kk < 16; kk++) {
            float a[8], b[8];
#pragma unroll
            for (int i = 0; i < 8; i++) a[i] = As[kk][ty * 8 + i];
#pragma unroll
            for (int j = 0; j < 8; j++) b[j] = Bs[kk][tx * 8 + j];
#pragma unroll
            for (int i = 0; i < 8; i++)
#pragma unroll
                for (int j = 0; j < 8; j++) acc[i][j] = fmaf(a[i], b[j], acc[i][j]);
        }
        __syncthreads();
    }
#pragma unroll
    for (int i = 0; i < 8; i++) {
        int gm = m0 + ty * 8 + i;
        if (gm >= M) continue;
#pragma unroll
        for (int j = 0; j < 8; j++) {
            int gn = n0 + tx * 8 + j;
            if (gn < N) epi(gm, gn, bz, acc[i][j]);
        }
    }
}

// ---------------- LN over 128 per (bt, k, n) -> x_head ----------------
__global__ void k_ln_head(const float* __restrict__ sc, const float* __restrict__ bi) {
    int bt = blockIdx.x, z = blockIdx.y;
    int kk = z >> 2, n = z & 3;
    int ns = g_invp[kk][n];
    int slot = g_slot[kk];
    const float* src = g_z1 + ((size_t)bt * 4 + ns) * DD + slot * DH;
    int tid = threadIdx.x;
    __shared__ float red[4];
    float v = src[tid];
    float mu = block_sum<4>(v, red) * (1.f / 128.f);
    float d = v - mu;
    float var = block_sum<4>(d * d, red) * (1.f / 128.f);
    g_xh[((size_t)bt * NH + z) * DH + tid] = d * rsqrtf(var + EPSF) * sc[tid] + bi[tid];
}

// ---------------- row softmax over 1024 ----------------
__global__ void k_softmax() {
    __shared__ float red[8];
    size_t base = (((size_t)blockIdx.y << 10) + blockIdx.x) << 10;
    float* p = g_sc + base;
    int tid = threadIdx.x;
    float v[4];
#pragma unroll
    for (int i = 0; i < 4; i++) v[i] = p[tid + (i << 8)];
    float mx = fmaxf(fmaxf(v[0], v[1]), fmaxf(v[2], v[3]));
    mx = block_max<8>(mx, red);
    float s = 0.f;
#pragma unroll
    for (int i = 0; i < 4; i++) { v[i] = __expf(v[i] - mx); s += v[i]; }
    s = block_sum<8>(s, red);
    float inv = 1.f / s;
#pragma unroll
    for (int i = 0; i < 4; i++) p[tid + (i << 8)] = v[i] * inv;
}

// ---------------- LN over 896 ----------------
__global__ void k_ln_mixer(const float* __restrict__ sc, const float* __restrict__ bi) {
    __shared__ float red[8];
    size_t row = blockIdx.x;
    const float* src = g_z1 + row * DD;
    float* dst = g_hm + row * DD;
    int tid = threadIdx.x;
    float v[4];
    float s = 0.f;
#pragma unroll
    for (int i = 0; i < 4; i++) {
        int c = tid + i * 256;
        v[i] = (c < DD) ? src[c] : 0.f;
        s += v[i];
    }
    s = block_sum<8>(s, red);
    float mu = s * (1.f / 896.f);
    float q = 0.f;
#pragma unroll
    for (int i = 0; i < 4; i++) {
        int c = tid + i * 256;
        if (c < DD) { float d = v[i] - mu; q += d * d; }
    }
    q = block_sum<8>(q, red);
    float r = rsqrtf(q * (1.f / 896.f) + EPSF);
#pragma unroll
    for (int i = 0; i < 4; i++) {
        int c = tid + i * 256;
        if (c < DD) dst[c] = (v[i] - mu) * r * sc[c] + bi[c];
    }
}

// ---------------- LN over 3584 ----------------
__global__ void k_ln_dec(const float* __restrict__ sc, const float* __restrict__ bi) {
    __shared__ float red[8];
    size_t row = blockIdx.x;
    const float* src = g_z1 + row * NDD;
    float* dst = g_hm + row * NDD;
    int tid = threadIdx.x;
    float v[14];
    float s = 0.f;
#pragma unroll
    for (int i = 0; i < 14; i++) { v[i] = src[tid + i * 256]; s += v[i]; }
    s = block_sum<8>(s, red);
    float mu = s * (1.f / 3584.f);
    float q = 0.f;
#pragma unroll
    for (int i = 0; i < 14; i++) { float d = v[i] - mu; q += d * d; }
    q = block_sum<8>(q, red);
    float r = rsqrtf(q * (1.f / 3584.f) + EPSF);
#pragma unroll
    for (int i = 0; i < 14; i++) {
        int c = tid + i * 256;
        dst[c] = (v[i] - mu) * r * sc[c] + bi[c];
    }
}

// ---------------- host launch ----------------
static inline float* sym_addr_f(const void* symbol) {
    void* p = nullptr;
    cudaGetSymbolAddress(&p, symbol);
    return (float*)p;
}

extern "C" void kernel_launch(void* const* d_in, const int* in_sizes, int n_in,
                              void* d_out, int out_size) {
    (void)in_sizes; (void)n_in; (void)out_size;
    const float* x          = (const float*)d_in[0];
    const float* enc_base_w = (const float*)d_in[1];
    const float* enc_A_w    = (const float*)d_in[2];
    const float* enc_B      = (const float*)d_in[3];
    const float* enc_beta   = (const float*)d_in[4];
    const float* Wqkv       = (const float*)d_in[5];
    const float* ln_attn_s  = (const float*)d_in[6];
    const float* ln_attn_b  = (const float*)d_in[7];
    const float* ln_mix_s   = (const float*)d_in[8];
    const float* ln_mix_b   = (const float*)d_in[9];
    const float* w1         = (const float*)d_in[10];
    const float* b1         = (const float*)d_in[11];
    const float* w2         = (const float*)d_in[12];
    const float* b2         = (const float*)d_in[13];
    const float* dls        = (const float*)d_in[14];
    const float* dlb        = (const float*)d_in[15];
    const float* down       = (const float*)d_in[16];
    const float* up         = (const float*)d_in[17];
    const int*   phase      = (const int*)d_in[18];
    float* out = (float*)d_out;

    float* p_h   = sym_addr_f(g_h);
    float* p_hm  = sym_addr_f(g_hm);
    float* p_hid = sym_addr_f(g_hidden);
    float* p_xh  = sym_addr_f(g_xh);
    float* p_q   = sym_addr_f(g_q);
    float* p_k   = sym_addr_f(g_k);
    float* p_v   = sym_addr_f(g_v);
    float* p_sc  = sym_addr_f(g_sc);
    float* p_dec = sym_addr_f(g_dec);

    // 0. scalars + phase tables
    k_scalars<<<1, 1>>>(enc_beta, phase);

    // 1. h = x @ enc_A_w.T  (fp32; feeds beta-scaled delta, keep exact)
    gemm<true><<<dim3(1, 64, 1), 256>>>(
        x, enc_A_w, BTOK, RNK, IOD, IOD, IOD, 0, 0, EpiH{});

    // 2. base = x @ enc_base_w.T -> broadcast to z0  (tf32 NT)
    tgemm<true, false, false><<<dim3(7, 64, 1), 256>>>(
        x, enc_base_w, BTOK, DD, IOD, IOD, IOD, 0, 0, EpiBase{});

    // 3. z0 += beta * (h @ enc_B)  (tf32 NN)
    tgemm<false, false, false><<<dim3(28, 64, 1), 256>>>(
        p_h, enc_B, BTOK, NDD, RNK, RNK, NDD, 0, 0, EpiDelta{});

    // 4. LN over slot heads -> x_head
    k_ln_head<<<dim3(BTOK, NH), 128>>>(ln_attn_s, ln_attn_b);

    // 5. qkv (tf32 NN, batched 12)
    tgemm<false, false, false><<<dim3(3, 64, 12), 256>>>(
        p_xh, Wqkv, BTOK, 3 * DH, DH, NH * DH, 3 * DH,
        (long)DH, (long)DH * 3 * DH, EpiQKV{});

    // 6. scores (tf32 NT, causal skip)
    tgemm<true, true, false><<<dim3(8, 8, BB * NH), 256>>>(
        p_q, p_k, TT, TT, DH, DH, DH,
        (long)TT * DH, (long)TT * DH, EpiScore{});

    // 7. softmax
    k_softmax<<<dim3(TT, BB * NH), 256>>>();

    // 8. out = P @ V (tf32 NN, causal k-clip), accumulate into z1
    tgemm<false, false, true><<<dim3(1, 8, BB * NH), 256>>>(
        p_sc, p_v, TT, DH, TT, TT, DH,
        (long)TT * TT, (long)TT * DH, EpiPV{});

    // 9. mixer LN
    k_ln_mixer<<<dim3(BTOK * N4), 256>>>(ln_mix_s, ln_mix_b);

    // 10. hidden = gelu(hm @ w1.T + b1)  (tf32 NT)
    tgemm<true, false, false><<<dim3(28, 256, 1), 256>>>(
        p_hm, w1, BTOK * N4, HID, DD, DD, DD, 0, 0, EpiGelu{b1});

    // 11. z2 = z1 + hidden @ w2.T + b2  (tf32 NT)
    tgemm<true, false, false><<<dim3(7, 256, 1), 256>>>(
        p_hid, w2, BTOK * N4, DD, HID, HID, HID, 0, 0, EpiMix2{b2});

    // 12. decoder LN
    k_ln_dec<<<dim3(BTOK), 256>>>(dls, dlb);

    // 13. dec = catln @ down.T  (tf32 NT, N=64 tile-guarded)
    tgemm<true, false, false><<<dim3(1, 64, 1), 256>>>(
        p_hm, down, BTOK, RNK, NDD, NDD, NDD, 0, 0, EpiDecD{});

    // 14. y = dec @ up.T  (fp32, final output, tiny K)
    gemm<true><<<dim3(8, 64, 1), 256>>>(
        p_dec, up, BTOK, IOD, RNK, RNK, RNK, 0, 0, EpiOut{out});
}

// round 4
// speedup vs baseline: 3.7311x; 1.0615x over previous
#include <cuda_runtime.h>
#include <math.h>
#include <stdint.h>

// ---------------- problem constants ----------------
#define BB   8
#define TT   1024
#define BTOK (BB*TT)          // 8192
#define N4   4
#define K3   3
#define DH   128
#define DD   896              // S*DH
#define NDD  3584             // N*D
#define HID  3584             // 4*D
#define IOD  1024
#define RNK  64
#define NH   12               // N*K heads
#define EPSF 1e-5f

// ---------------- device scratch ----------------
__device__ float g_beta;
__device__ int   g_slot[3];
__device__ int   g_invp[3][4];

__device__ __align__(16) float g_h[BTOK*RNK];
__device__ __align__(16) float g_z1[(size_t)BTOK*NDD];
__device__ __align__(16) float g_hm[(size_t)BTOK*NDD];
__device__ __align__(16) float g_hidden[(size_t)BTOK*4*HID];
__device__ __align__(16) float g_xh[(size_t)BTOK*NH*DH];
__device__ __align__(16) float g_q[(size_t)BB*NH*TT*DH];
__device__ __align__(16) float g_k[(size_t)BB*NH*TT*DH];
__device__ __align__(16) float g_v[(size_t)BB*NH*TT*DH];
__device__ __align__(16) float g_sc[(size_t)BB*NH*TT*TT];
__device__ __align__(16) float g_dec[BTOK*RNK];

// tf32-pre-rounded copies of external inputs that feed tensor GEMMs
__device__ __align__(16) float g_xr [(size_t)BTOK*IOD];
__device__ __align__(16) float g_wbr[(size_t)DD*IOD];
__device__ __align__(16) float g_ebr[(size_t)RNK*NDD];
__device__ __align__(16) float g_wqr[(size_t)K3*N4*DH*3*DH];
__device__ __align__(16) float g_w1r[(size_t)HID*DD];
__device__ __align__(16) float g_w2r[(size_t)DD*HID];

// ---------------- tf32 helpers ----------------
__device__ __forceinline__ uint32_t f2tf(float f) {
    uint32_t u; asm("cvt.rna.tf32.f32 %0, %1;" : "=r"(u) : "f"(f)); return u;
}
__device__ __forceinline__ float rtf(float f) {
    return __uint_as_float(f2tf(f));
}
__device__ __forceinline__ void mma_tf32(float* c, const uint32_t* a, const uint32_t* b) {
    asm volatile("mma.sync.aligned.m16n8k8.row.col.f32.tf32.tf32.f32 "
        "{%0,%1,%2,%3},{%4,%5,%6,%7},{%8,%9},{%0,%1,%2,%3};"
        : "+f"(c[0]), "+f"(c[1]), "+f"(c[2]), "+f"(c[3])
        : "r"(a[0]), "r"(a[1]), "r"(a[2]), "r"(a[3]), "r"(b[0]), "r"(b[1]));
}
__device__ __forceinline__ void cp16(uint32_t d, const void* g) {
    asm volatile("cp.async.cg.shared.global [%0], [%1], 16;\n" :: "r"(d), "l"(g) : "memory");
}

// ---------------- scalar / table prologue ----------------
__global__ void k_scalars(const float* beta, const int* phase) {
    g_beta = *beta;
    int ph = *phase;
    int off = 0;
    const int sc[3] = {1, 2, 4};
    for (int k = 0; k < 3; k++) {
        int s = sc[k];
        int j = ph % s;
        g_slot[k] = off + j;
        off += s;
        int alpha = 4 / s;
        for (int i = 0; i < 4; i++) {
            int p = (i + alpha * j) & 3;
            g_invp[k][p] = i;
        }
    }
}

// ---------------- tf32 pre-rounding copy ----------------
__global__ void k_round4(const float4* __restrict__ src, float4* __restrict__ dst, int n4) {
    int i = blockIdx.x * blockDim.x + threadIdx.x;
    if (i < n4) {
        float4 v = src[i];
        v.x = rtf(v.x); v.y = rtf(v.y); v.z = rtf(v.z); v.w = rtf(v.w);
        dst[i] = v;
    }
}

// ---------------- block reductions ----------------
template<int W>
__device__ __forceinline__ float block_sum(float x, float* red) {
#pragma unroll
    for (int o = 16; o > 0; o >>= 1) x += __shfl_xor_sync(0xffffffffu, x, o);
    __syncthreads();
    if ((threadIdx.x & 31) == 0) red[threadIdx.x >> 5] = x;
    __syncthreads();
    float s = 0.f;
#pragma unroll
    for (int i = 0; i < W; i++) s += red[i];
    return s;
}
template<int W>
__device__ __forceinline__ float block_max(float x, float* red) {
#pragma unroll
    for (int o = 16; o > 0; o >>= 1) x = fmaxf(x, __shfl_xor_sync(0xffffffffu, x, o));
    __syncthreads();
    if ((threadIdx.x & 31) == 0) red[threadIdx.x >> 5] = x;
    __syncthreads();
    float s = -1e30f;
#pragma unroll
    for (int i = 0; i < W; i++) s = fmaxf(s, red[i]);
    return s;
}

// ---------------- epilogue functors ----------------
struct EpiH {   // rounded: feeds tf32 delta gemm
    __device__ void operator()(int m, int n, int, float v) const { g_h[m*RNK + n] = rtf(v); }
};
struct EpiBase {
    __device__ void operator()(int m, int n, int, float v) const {
        size_t base = (size_t)m * NDD + n;
        g_z1[base] = v; g_z1[base + DD] = v; g_z1[base + 2*DD] = v; g_z1[base + 3*DD] = v;
    }
};
struct EpiDelta {
    __device__ void operator()(int m, int n, int, float v) const {
        g_z1[(size_t)m * NDD + n] += g_beta * v;
    }
};
struct EpiQKV { // rounded: q,k,v feed tf32 gemms
    __device__ void operator()(int m, int n, int bz, float v) const {
        int b = m >> 10, t = m & 1023;
        int kk = bz >> 2, ns = bz & 3;
        int h = g_invp[kk][ns] * 3 + kk;
        float* dst; int e = n;
        if (e < DH)            { dst = g_q; }
        else if (e < 2*DH)     { dst = g_k; e -= DH; }
        else                   { dst = g_v; e -= 2*DH; }
        dst[(((size_t)b * NH + h) * TT + t) * DH + e] = rtf(v);
    }
};
struct EpiScore {
    __device__ void operator()(int m, int n, int bz, float v) const {
        g_sc[((size_t)bz * TT + m) * TT + n] =
            (n <= m) ? v * 0.088388347648318447f : -1e9f;
    }
};
struct EpiPV {
    __device__ void operator()(int m, int n, int bz, float v) const {
        int b = bz / NH, h = bz % NH;
        int kk = h % 3, nn = h / 3;
        int slot = g_slot[kk];
        g_z1[(((size_t)(b * TT + m)) * N4 + nn) * DD + slot * DH + n] += v;
    }
};
struct EpiGelu { // rounded: feeds tf32 mixer2
    const float* b1;
    __device__ void operator()(int m, int n, int, float v) const {
        float u = v + b1[n];
        g_hidden[(size_t)m * HID + n] = rtf(0.5f * u * (1.f + erff(u * 0.70710678118654752f)));
    }
};
struct EpiMix2 {
    const float* b2;
    __device__ void operator()(int m, int n, int, float v) const {
        g_z1[(size_t)m * DD + n] += v + b2[n];
    }
};
struct EpiDecD {
    __device__ void operator()(int m, int n, int, float v) const { g_dec[m*RNK + n] = v; }
};
struct EpiOut {
    float* out;
    __device__ void operator()(int m, int n, int, float v) const { out[(size_t)m * IOD + n] = v; }
};

// ================= cp.async 3-stage pipelined tf32 GEMM =================
// Block tile 128x128, 4 warps (128 thr), warp tile 64x64.
// Inputs must already be tf32-rounded floats.
// Requires: M%128==0, Kd%32==0, lda%4==0, ldb%4==0, and for cp.async path
// the full 128-wide N tile must be in-bounds (all callers satisfy this).
// BT_=true: B row-major (N x K). BT_=false: B (K x N).
#define CG_STAGE 9216            // floats per stage (As 128*36 + Bs max 4608)
#define CG_SMEM  (3*CG_STAGE*4)  // bytes

template<bool BT_, bool CSKIP, bool CKLIM, class Epi>
__global__ void __launch_bounds__(128, 2)
cgemm(const float* __restrict__ A, const float* __restrict__ B,
      int M, int N, int Kd, int lda, int ldb, long sA, long sB, Epi epi)
{
    extern __shared__ float smem[];
    const int bz = blockIdx.z;
    A += (size_t)bz * sA;
    B += (size_t)bz * sB;
    const int m0 = blockIdx.y * 128, n0 = blockIdx.x * 128;
    const int tid = threadIdx.x;
    const int lane = tid & 31, wid = tid >> 5;
    const int wm = (wid & 1) * 64, wn = (wid >> 1) * 64;

    float c[32][4];
#pragma unroll
    for (int i = 0; i < 32; i++)
#pragma unroll
        for (int j = 0; j < 4; j++) c[i][j] = 0.f;

    if (!(CSKIP && n0 >= m0 + 128)) {
        int kEnd = CKLIM ? ((Kd < m0 + 128) ? Kd : (m0 + 128)) : Kd;
        int ntile = kEnd >> 5;

        auto issue = [&](int t) {
            float* As = smem + (t % 3) * CG_STAGE;
            float* Bs = As + 4608;
            uint32_t as_b = (uint32_t)__cvta_generic_to_shared(As);
            uint32_t bs_b = (uint32_t)__cvta_generic_to_shared(Bs);
            int k0 = t * 32;
            // A tile: 128 rows x 32k  (8 x 16B chunks per row)
#pragma unroll
            for (int i = 0; i < 8; i++) {
                int idx = i * 128 + tid;
                int r = idx >> 3, cq = (idx & 7) * 4;
                cp16(as_b + (uint32_t)(r * 36 + cq) * 4,
                     A + (size_t)(m0 + r) * lda + k0 + cq);
            }
            if (BT_) {
#pragma unroll
                for (int i = 0; i < 8; i++) {
                    int idx = i * 128 + tid;
                    int r = idx >> 3, cq = (idx & 7) * 4;
                    cp16(bs_b + (uint32_t)(r * 36 + cq) * 4,
                         B + (size_t)(n0 + r) * ldb + k0 + cq);
                }
            } else {
                // B tile 32k x 128n, store as Bs[k][n] stride 132
#pragma unroll
                for (int i = 0; i < 8; i++) {
                    int idx = i * 128 + tid;
                    int r = idx >> 5, cq = (idx & 31) * 4;
                    cp16(bs_b + (uint32_t)(r * 132 + cq) * 4,
                         B + (size_t)(k0 + r) * ldb + n0 + cq);
                }
            }
            asm volatile("cp.async.commit_group;\n" ::);
        };

        int npro = ntile < 2 ? ntile : 2;
        for (int s = 0; s < npro; s++) issue(s);

        for (int t = 0; t < ntile; t++) {
            if (t == ntile - 1) asm volatile("cp.async.wait_group 0;\n" ::: "memory");
            else                asm volatile("cp.async.wait_group 1;\n" ::: "memory");
            __syncthreads();
            if (t + 2 < ntile) issue(t + 2);

            const float* As = smem + (t % 3) * CG_STAGE;
            const float* Bs = As + 4608;
            const int ar = lane >> 2;
#pragma unroll
            for (int ks = 0; ks < 4; ks++) {
                const int ac = ks * 8 + (lane & 3);
                uint32_t a[4][4], b[8][2];
#pragma unroll
                for (int mt = 0; mt < 4; mt++) {
                    int row = wm + mt * 16 + ar;
                    a[mt][0] = __float_as_uint(As[row * 36 + ac]);
                    a[mt][1] = __float_as_uint(As[(row + 8) * 36 + ac]);
                    a[mt][2] = __float_as_uint(As[row * 36 + ac + 4]);
                    a[mt][3] = __float_as_uint(As[(row + 8) * 36 + ac + 4]);
                }
#pragma unroll
                for (int nt8 = 0; nt8 < 8; nt8++) {
                    int col = wn + nt8 * 8 + ar;
                    if (BT_) {
                        b[nt8][0] = __float_as_uint(Bs[col * 36 + ac]);
                        b[nt8][1] = __float_as_uint(Bs[col * 36 + ac + 4]);
                    } else {
                        b[nt8][0] = __float_as_uint(Bs[ac * 132 + col]);
                        b[nt8][1] = __float_as_uint(Bs[(ac + 4) * 132 + col]);
                    }
                }
#pragma unroll
                for (int mt = 0; mt < 4; mt++)
#pragma unroll
                    for (int nt8 = 0; nt8 < 8; nt8++)
                        mma_tf32(c[mt * 8 + nt8], a[mt], b[nt8]);
            }
        }
    }
    // ---- epilogue ----
#pragma unroll
    for (int mt = 0; mt < 4; mt++)
#pragma unroll
        for (int nt8 = 0; nt8 < 8; nt8++)
#pragma unroll
            for (int r = 0; r < 4; r++) {
                int gm = m0 + wm + mt * 16 + (lane >> 2) + (r >> 1) * 8;
                int gn = n0 + wn + nt8 * 8 + (lane & 3) * 2 + (r & 1);
                epi(gm, gn, bz, c[mt * 8 + nt8][r]);
            }
}

// ================= register-prefetch tf32 GEMM (N-guarded; for N=64 case) =================
template<bool BT_, class Epi>
__global__ void __launch_bounds__(256, 2)
tgemm(const float* __restrict__ A, const float* __restrict__ B,
      int M, int N, int Kd, int lda, int ldb, long sA, long sB, Epi epi)
{
    const int bz = blockIdx.z;
    A += (size_t)bz * sA;
    B += (size_t)bz * sB;
    const int m0 = blockIdx.y * 128, n0 = blockIdx.x * 128;
    const int tid = threadIdx.x;
    const int lane = tid & 31, wid = tid >> 5;
    const int wm = (wid & 1) * 64, wn = (wid >> 1) * 32;

    __shared__ uint32_t As[128][36];
    __shared__ uint32_t Bs[128][36];

    float c[16][4];
#pragma unroll
    for (int i = 0; i < 16; i++)
#pragma unroll
        for (int j = 0; j < 4; j++) c[i][j] = 0.f;

    {
        int kEnd = Kd;
        const int arw = tid >> 3, aq = (tid & 7) * 4;
        float4 ra[4];
        float  rb[16];
        {
#pragma unroll
            for (int i = 0; i < 4; i++)
                ra[i] = *(const float4*)(A + (size_t)(m0 + arw + i * 32) * lda + aq);
#pragma unroll
            for (int i = 0; i < 4; i++) {
                int gn = n0 + arw + i * 32;
                float4 f = (gn < N) ? *(const float4*)(B + (size_t)gn * ldb + aq)
                                    : make_float4(0.f, 0.f, 0.f, 0.f);
                rb[i*4+0] = f.x; rb[i*4+1] = f.y; rb[i*4+2] = f.z; rb[i*4+3] = f.w;
            }
        }
        for (int k0 = 0; k0 < kEnd; k0 += 32) {
#pragma unroll
            for (int i = 0; i < 4; i++) {
                uint4 u;
                u.x = f2tf(ra[i].x); u.y = f2tf(ra[i].y);
                u.z = f2tf(ra[i].z); u.w = f2tf(ra[i].w);
                *(uint4*)&As[arw + i * 32][aq] = u;
            }
#pragma unroll
            for (int i = 0; i < 4; i++) {
                uint4 u;
                u.x = f2tf(rb[i*4+0]); u.y = f2tf(rb[i*4+1]);
                u.z = f2tf(rb[i*4+2]); u.w = f2tf(rb[i*4+3]);
                *(uint4*)&Bs[arw + i * 32][aq] = u;
            }
            __syncthreads();
            if (k0 + 32 < kEnd) {
                int kn = k0 + 32;
#pragma unroll
                for (int i = 0; i < 4; i++)
                    ra[i] = *(const float4*)(A + (size_t)(m0 + arw + i * 32) * lda + kn + aq);
#pragma unroll
                for (int i = 0; i < 4; i++) {
                    int gn = n0 + arw + i * 32;
                    float4 f = (gn < N) ? *(const float4*)(B + (size_t)gn * ldb + kn + aq)
                                        : make_float4(0.f, 0.f, 0.f, 0.f);
                    rb[i*4+0] = f.x; rb[i*4+1] = f.y; rb[i*4+2] = f.z; rb[i*4+3] = f.w;
                }
            }
#pragma unroll
            for (int ks = 0; ks < 4; ks++) {
                int kk = ks * 8;
                uint32_t a[4][4], b[4][2];
                int ar = lane >> 2, ac = kk + (lane & 3);
#pragma unroll
                for (int mt = 0; mt < 4; mt++) {
                    int row = wm + mt * 16 + ar;
                    a[mt][0] = As[row][ac];
                    a[mt][1] = As[row + 8][ac];
                    a[mt][2] = As[row][ac + 4];
                    a[mt][3] = As[row + 8][ac + 4];
                }
#pragma unroll
                for (int nt = 0; nt < 4; nt++) {
                    int col = wn + nt * 8 + ar;
                    b[nt][0] = Bs[col][ac];
                    b[nt][1] = Bs[col][ac + 4];
                }
#pragma unroll
                for (int mt = 0; mt < 4; mt++)
#pragma unroll
                    for (int nt = 0; nt < 4; nt++)
                        mma_tf32(c[mt * 4 + nt], a[mt], b[nt]);
            }
            __syncthreads();
        }
    }
#pragma unroll
    for (int mt = 0; mt < 4; mt++)
#pragma unroll
        for (int nt = 0; nt < 4; nt++)
#pragma unroll
            for (int r = 0; r < 4; r++) {
                int gm = m0 + wm + mt * 16 + (lane >> 2) + (r >> 1) * 8;
                int gn = n0 + wn + nt * 8 + (lane & 3) * 2 + (r & 1);
                if (gn < N) epi(gm, gn, bz, c[mt * 4 + nt][r]);
            }
}

// ---------------- fp32 tiled GEMM ----------------
template<bool BT_, class Epi>
__global__ void __launch_bounds__(256, 2)
gemm(const float* __restrict__ A, const float* __restrict__ B,
     int M, int N, int Kd, int lda, int ldb, long sA, long sB, Epi epi)
{
    const int bz = blockIdx.z;
    A += (size_t)bz * sA;
    B += (size_t)bz * sB;
    const int m0 = blockIdx.y * 128, n0 = blockIdx.x * 128;
    const int tid = threadIdx.x, tx = tid & 15, ty = tid >> 4;

    __shared__ float As[16][132];
    __shared__ float Bs[16][132];

    float acc[8][8];
#pragma unroll
    for (int i = 0; i < 8; i++)
#pragma unroll
        for (int j = 0; j < 8; j++) acc[i][j] = 0.f;

    for (int k0 = 0; k0 < Kd; k0 += 16) {
#pragma unroll
        for (int i = 0; i < 8; i++) {
            int idx = i * 256 + tid;
            int mm = idx >> 4, kk = idx & 15;
            int gm = m0 + mm, gk = k0 + kk;
            As[kk][mm] = (gm < M && gk < Kd) ? A[(size_t)gm * lda + gk] : 0.f;
        }
        if (BT_) {
#pragma unroll
            for (int i = 0; i < 8; i++) {
                int idx = i * 256 + tid;
                int nn = idx >> 4, kk = idx & 15;
                int gn = n0 + nn, gk = k0 + kk;
                Bs[kk][nn] = (gn < N && gk < Kd) ? B[(size_t)gn * ldb + gk] : 0.f;
            }
        } else {
#pragma unroll
            for (int i = 0; i < 8; i++) {
                int idx = i * 256 + tid;
                int nn = idx & 127, kk = idx >> 7;
                int gn = n0 + nn, gk = k0 + kk;
                Bs[kk][nn] = (gn < N && gk < Kd) ? B[(size_t)gk * ldb + gn] : 0.f;
            }
        }
        __syncthreads();
#pragma unroll
        for (int kk = 0; kk < 16; kk++) {
            float a[8], b[8];
#pragma unroll
            for (int i = 0; i < 8; i++) a[i] = As[kk][ty * 8 + i];
#pragma unroll
            for (int j = 0; j < 8; j++) b[j] = Bs[kk][tx * 8 + j];
#pragma unroll
            for (int i = 0; i < 8; i++)
#pragma unroll
                for (int j = 0; j < 8; j++) acc[i][j] = fmaf(a[i], b[j], acc[i][j]);
        }
        __syncthreads();
    }
#pragma unroll
    for (int i = 0; i < 8; i++) {
        int gm = m0 + ty * 8 + i;
        if (gm >= M) continue;
#pragma unroll
        for (int j = 0; j < 8; j++) {
            int gn = n0 + tx * 8 + j;
            if (gn < N) epi(gm, gn, bz, acc[i][j]);
        }
    }
}

// ---------------- LN over 128 per (bt, k, n) -> x_head (rounded) ----------------
__global__ void k_ln_head(const float* __restrict__ sc, const float* __restrict__ bi) {
    int bt = blockIdx.x, z = blockIdx.y;
    int kk = z >> 2, n = z & 3;
    int ns = g_invp[kk][n];
    int slot = g_slot[kk];
    const float* src = g_z1 + ((size_t)bt * 4 + ns) * DD + slot * DH;
    int tid = threadIdx.x;
    __shared__ float red[4];
    float v = src[tid];
    float mu = block_sum<4>(v, red) * (1.f / 128.f);
    float d = v - mu;
    float var = block_sum<4>(d * d, red) * (1.f / 128.f);
    g_xh[((size_t)bt * NH + z) * DH + tid] = rtf(d * rsqrtf(var + EPSF) * sc[tid] + bi[tid]);
}

// ---------------- row softmax over 1024 (rounded output) ----------------
__global__ void k_softmax() {
    __shared__ float red[8];
    size_t base = (((size_t)blockIdx.y << 10) + blockIdx.x) << 10;
    float* p = g_sc + base;
    int tid = threadIdx.x;
    float v[4];
#pragma unroll
    for (int i = 0; i < 4; i++) v[i] = p[tid + (i << 8)];
    float mx = fmaxf(fmaxf(v[0], v[1]), fmaxf(v[2], v[3]));
    mx = block_max<8>(mx, red);
    float s = 0.f;
#pragma unroll
    for (int i = 0; i < 4; i++) { v[i] = __expf(v[i] - mx); s += v[i]; }
    s = block_sum<8>(s, red);
    float inv = 1.f / s;
#pragma unroll
    for (int i = 0; i < 4; i++) p[tid + (i << 8)] = rtf(v[i] * inv);
}

// ---------------- LN over 896 (rounded output: feeds tf32 mixer1) ----------------
__global__ void k_ln_mixer(const float* __restrict__ sc, const float* __restrict__ bi) {
    __shared__ float red[8];
    size_t row = blockIdx.x;
    const float* src = g_z1 + row * DD;
    float* dst = g_hm + row * DD;
    int tid = threadIdx.x;
    float v[4];
    float s = 0.f;
#pragma unroll
    for (int i = 0; i < 4; i++) {
        int c = tid + i * 256;
        v[i] = (c < DD) ? src[c] : 0.f;
        s += v[i];
    }
    s = block_sum<8>(s, red);
    float mu = s * (1.f / 896.f);
    float q = 0.f;
#pragma unroll
    for (int i = 0; i < 4; i++) {
        int c = tid + i * 256;
        if (c < DD) { float d = v[i] - mu; q += d * d; }
    }
    q = block_sum<8>(q, red);
    float r = rsqrtf(q * (1.f / 896.f) + EPSF);
#pragma unroll
    for (int i = 0; i < 4; i++) {
        int c = tid + i * 256;
        if (c < DD) dst[c] = rtf((v[i] - mu) * r * sc[c] + bi[c]);
    }
}

// ---------------- LN over 3584 ----------------
__global__ void k_ln_dec(const float* __restrict__ sc, const float* __restrict__ bi) {
    __shared__ float red[8];
    size_t row = blockIdx.x;
    const float* src = g_z1 + row * NDD;
    float* dst = g_hm + row * NDD;
    int tid = threadIdx.x;
    float v[14];
    float s = 0.f;
#pragma unroll
    for (int i = 0; i < 14; i++) { v[i] = src[tid + i * 256]; s += v[i]; }
    s = block_sum<8>(s, red);
    float mu = s * (1.f / 3584.f);
    float q = 0.f;
#pragma unroll
    for (int i = 0; i < 14; i++) { float d = v[i] - mu; q += d * d; }
    q = block_sum<8>(q, red);
    float r = rsqrtf(q * (1.f / 3584.f) + EPSF);
#pragma unroll
    for (int i = 0; i < 14; i++) {
        int c = tid + i * 256;
        dst[c] = (v[i] - mu) * r * sc[c] + bi[c];
    }
}

// ---------------- host launch ----------------
static inline float* sym_addr_f(const void* symbol) {
    void* p = nullptr;
    cudaGetSymbolAddress(&p, symbol);
    return (float*)p;
}

extern "C" void kernel_launch(void* const* d_in, const int* in_sizes, int n_in,
                              void* d_out, int out_size) {
    (void)in_sizes; (void)n_in; (void)out_size;
    const float* x          = (const float*)d_in[0];
    const float* enc_base_w = (const float*)d_in[1];
    const float* enc_A_w    = (const float*)d_in[2];
    const float* enc_B      = (const float*)d_in[3];
    const float* enc_beta   = (const float*)d_in[4];
    const float* Wqkv       = (const float*)d_in[5];
    const float* ln_attn_s  = (const float*)d_in[6];
    const float* ln_attn_b  = (const float*)d_in[7];
    const float* ln_mix_s   = (const float*)d_in[8];
    const float* ln_mix_b   = (const float*)d_in[9];
    const float* w1         = (const float*)d_in[10];
    const float* b1         = (const float*)d_in[11];
    const float* w2         = (const float*)d_in[12];
    const float* b2         = (const float*)d_in[13];
    const float* dls        = (const float*)d_in[14];
    const float* dlb        = (const float*)d_in[15];
    const float* down       = (const float*)d_in[16];
    const float* up         = (const float*)d_in[17];
    const int*   phase      = (const int*)d_in[18];
    float* out = (float*)d_out;

    float* p_h   = sym_addr_f(g_h);
    float* p_hm  = sym_addr_f(g_hm);
    float* p_hid = sym_addr_f(g_hidden);
    float* p_xh  = sym_addr_f(g_xh);
    float* p_q   = sym_addr_f(g_q);
    float* p_k   = sym_addr_f(g_k);
    float* p_v   = sym_addr_f(g_v);
    float* p_sc  = sym_addr_f(g_sc);
    float* p_dec = sym_addr_f(g_dec);
    float* p_xr  = sym_addr_f(g_xr);
    float* p_wbr = sym_addr_f(g_wbr);
    float* p_ebr = sym_addr_f(g_ebr);
    float* p_wqr = sym_addr_f(g_wqr);
    float* p_w1r = sym_addr_f(g_w1r);
    float* p_w2r = sym_addr_f(g_w2r);

    // enable >48KB dynamic smem for all cgemm instantiations (idempotent)
    cudaFuncSetAttribute(cgemm<true,  false, false, EpiBase >, cudaFuncAttributeMaxDynamicSharedMemorySize, CG_SMEM);
    cudaFuncSetAttribute(cgemm<false, false, false, EpiDelta>, cudaFuncAttributeMaxDynamicSharedMemorySize, CG_SMEM);
    cudaFuncSetAttribute(cgemm<false, false, false, EpiQKV  >, cudaFuncAttributeMaxDynamicSharedMemorySize, CG_SMEM);
    cudaFuncSetAttribute(cgemm<true,  true,  false, EpiScore>, cudaFuncAttributeMaxDynamicSharedMemorySize, CG_SMEM);
    cudaFuncSetAttribute(cgemm<false, false, true,  EpiPV   >, cudaFuncAttributeMaxDynamicSharedMemorySize, CG_SMEM);
    cudaFuncSetAttribute(cgemm<true,  false, false, EpiGelu >, cudaFuncAttributeMaxDynamicSharedMemorySize, CG_SMEM);
    cudaFuncSetAttribute(cgemm<true,  false, false, EpiMix2 >, cudaFuncAttributeMaxDynamicSharedMemorySize, CG_SMEM);

    // 0. scalars + phase tables
    k_scalars<<<1, 1>>>(enc_beta, phase);

    // 0b. tf32 pre-rounding of external gemm inputs
    k_round4<<<(BTOK*IOD/4 + 255)/256, 256>>>((const float4*)x,          (float4*)p_xr,  BTOK*IOD/4);
    k_round4<<<(DD*IOD/4   + 255)/256, 256>>>((const float4*)enc_base_w, (float4*)p_wbr, DD*IOD/4);
    k_round4<<<(RNK*NDD/4  + 255)/256, 256>>>((const float4*)enc_B,      (float4*)p_ebr, RNK*NDD/4);
    k_round4<<<(K3*N4*DH*3*DH/4 + 255)/256, 256>>>((const float4*)Wqkv,  (float4*)p_wqr, K3*N4*DH*3*DH/4);
    k_round4<<<((size_t)HID*DD/4 + 255)/256, 256>>>((const float4*)w1,   (float4*)p_w1r, HID*DD/4);
    k_round4<<<((size_t)DD*HID/4 + 255)/256, 256>>>((const float4*)w2,   (float4*)p_w2r, DD*HID/4);

    // 1. h = x @ enc_A_w.T  (fp32; epilogue rounds for tf32 delta gemm)
    gemm<true><<<dim3(1, 64, 1), 256>>>(
        x, enc_A_w, BTOK, RNK, IOD, IOD, IOD, 0, 0, EpiH{});

    // 2. base = x @ enc_base_w.T -> broadcast to z0  (tf32 NT)
    cgemm<true, false, false><<<dim3(7, 64, 1), 128, CG_SMEM>>>(
        p_xr, p_wbr, BTOK, DD, IOD, IOD, IOD, 0, 0, EpiBase{});

    // 3. z0 += beta * (h @ enc_B)  (tf32 NN)
    cgemm<false, false, false><<<dim3(28, 64, 1), 128, CG_SMEM>>>(
        p_h, p_ebr, BTOK, NDD, RNK, RNK, NDD, 0, 0, EpiDelta{});

    // 4. LN over slot heads -> x_head (rounded)
    k_ln_head<<<dim3(BTOK, NH), 128>>>(ln_attn_s, ln_attn_b);

    // 5. qkv (tf32 NN, batched 12)
    cgemm<false, false, false><<<dim3(3, 64, 12), 128, CG_SMEM>>>(
        p_xh, p_wqr, BTOK, 3 * DH, DH, NH * DH, 3 * DH,
        (long)DH, (long)DH * 3 * DH, EpiQKV{});

    // 6. scores (tf32 NT, causal skip)
    cgemm<true, true, false><<<dim3(8, 8, BB * NH), 128, CG_SMEM>>>(
        p_q, p_k, TT, TT, DH, DH, DH,
        (long)TT * DH, (long)TT * DH, EpiScore{});

    // 7. softmax (rounded output)
    k_softmax<<<dim3(TT, BB * NH), 256>>>();

    // 8. out = P @ V (tf32 NN, causal k-clip), accumulate into z1
    cgemm<false, false, true><<<dim3(1, 8, BB * NH), 128, CG_SMEM>>>(
        p_sc, p_v, TT, DH, TT, TT, DH,
        (long)TT * TT, (long)TT * DH, EpiPV{});

    // 9. mixer LN (rounded output)
    k_ln_mixer<<<dim3(BTOK * N4), 256>>>(ln_mix_s, ln_mix_b);

    // 10. hidden = gelu(hm @ w1.T + b1)  (tf32 NT)
    cgemm<true, false, false><<<dim3(28, 256, 1), 128, CG_SMEM>>>(
        p_hm, p_w1r, BTOK * N4, HID, DD, DD, DD, 0, 0, EpiGelu{b1});

    // 11. z2 = z1 + hidden @ w2.T + b2  (tf32 NT)
    cgemm<true, false, false><<<dim3(7, 256, 1), 128, CG_SMEM>>>(
        p_hid, p_w2r, BTOK * N4, DD, HID, HID, HID, 0, 0, EpiMix2{b2});

    // 12. decoder LN
    k_ln_dec<<<dim3(BTOK), 256>>>(dls, dlb);

    // 13. dec = catln @ down.T  (tf32 NT, N=64 guarded -> old tgemm)
    tgemm<true><<<dim3(1, 64, 1), 256>>>(
        p_hm, down, BTOK, RNK, NDD, NDD, NDD, 0, 0, EpiDecD{});

    // 14. y = dec @ up.T  (fp32, final output, tiny K)
    gemm<true><<<dim3(8, 64, 1), 256>>>(
        p_dec, up, BTOK, IOD, RNK, RNK, RNK, 0, 0, EpiOut{out});
}

// round 6
// speedup vs baseline: 3.8139x; 1.0222x over previous
#include <cuda_runtime.h>
#include <cuda_fp16.h>
#include <math.h>
#include <stdint.h>

// ---------------- problem constants ----------------
#define BB   8
#define TT   1024
#define BTOK (BB*TT)          // 8192
#define N4   4
#define K3   3
#define DH   128
#define DD   896              // S*DH
#define NDD  3584             // N*D
#define HID  3584             // 4*D
#define IOD  1024
#define RNK  64
#define NH   12               // N*K heads
#define EPSF 1e-5f

// ---------------- device scratch ----------------
__device__ float g_beta;
__device__ int   g_slot[3];
__device__ int   g_invp[3][4];

__device__ __align__(16) __half g_h[BTOK*RNK];
__device__ __align__(16) float  g_z1[(size_t)BTOK*NDD];
__device__ __align__(16) float  g_hm[(size_t)BTOK*NDD];          // dec LN out (fp32)
__device__ __align__(16) __half g_hmh[(size_t)BTOK*NDD];         // mixer LN out (fp16)
__device__ __align__(16) __half g_hidden[(size_t)BTOK*4*HID];
__device__ __align__(16) __half g_xhh[(size_t)BTOK*NH*DH];
__device__ __align__(16) __half g_q[(size_t)BB*NH*TT*DH];
__device__ __align__(16) __half g_k[(size_t)BB*NH*TT*DH];
__device__ __align__(16) __half g_v[(size_t)BB*NH*TT*DH];
__device__ __align__(16) float  g_sc[(size_t)BB*NH*TT*TT];       // scores fp32
__device__ __align__(16) __half g_ph[(size_t)BB*NH*TT*TT];       // probs fp16
__device__ __align__(16) float  g_dec[BTOK*RNK];

// fp16 copies of external inputs feeding tensor GEMMs
__device__ __align__(16) __half g_xH [(size_t)BTOK*IOD];
__device__ __align__(16) __half g_wbH[(size_t)DD*IOD];
__device__ __align__(16) __half g_ebH[(size_t)RNK*NDD];
__device__ __align__(16) __half g_wqH[(size_t)K3*N4*DH*3*DH];
__device__ __align__(16) __half g_w1H[(size_t)HID*DD];
__device__ __align__(16) __half g_w2H[(size_t)DD*HID];

// ---------------- low-level helpers ----------------
__device__ __forceinline__ uint32_t f2tf(float f) {
    uint32_t u; asm("cvt.rna.tf32.f32 %0, %1;" : "=r"(u) : "f"(f)); return u;
}
__device__ __forceinline__ void mma_tf32(float* c, const uint32_t* a, const uint32_t* b) {
    asm volatile("mma.sync.aligned.m16n8k8.row.col.f32.tf32.tf32.f32 "
        "{%0,%1,%2,%3},{%4,%5,%6,%7},{%8,%9},{%0,%1,%2,%3};"
        : "+f"(c[0]), "+f"(c[1]), "+f"(c[2]), "+f"(c[3])
        : "r"(a[0]), "r"(a[1]), "r"(a[2]), "r"(a[3]), "r"(b[0]), "r"(b[1]));
}
__device__ __forceinline__ void mma_f16(float* c, const uint32_t* a, const uint32_t* b) {
    asm volatile("mma.sync.aligned.m16n8k16.row.col.f32.f16.f16.f32 "
        "{%0,%1,%2,%3},{%4,%5,%6,%7},{%8,%9},{%0,%1,%2,%3};"
        : "+f"(c[0]), "+f"(c[1]), "+f"(c[2]), "+f"(c[3])
        : "r"(a[0]), "r"(a[1]), "r"(a[2]), "r"(a[3]), "r"(b[0]), "r"(b[1]));
}
__device__ __forceinline__ void cp16(uint32_t d, const void* g) {
    asm volatile("cp.async.cg.shared.global [%0], [%1], 16;\n" :: "r"(d), "l"(g) : "memory");
}
__device__ __forceinline__ void ldsm4(uint32_t* r, uint32_t a) {
    asm volatile("ldmatrix.sync.aligned.m8n8.x4.shared.b16 {%0,%1,%2,%3}, [%4];"
        : "=r"(r[0]), "=r"(r[1]), "=r"(r[2]), "=r"(r[3]) : "r"(a));
}
__device__ __forceinline__ void ldsm4t(uint32_t* r, uint32_t a) {
    asm volatile("ldmatrix.sync.aligned.m8n8.x4.trans.shared.b16 {%0,%1,%2,%3}, [%4];"
        : "=r"(r[0]), "=r"(r[1]), "=r"(r[2]), "=r"(r[3]) : "r"(a));
}

// ---------------- scalar / table prologue ----------------
__global__ void k_scalars(const float* beta, const int* phase) {
    g_beta = *beta;
    int ph = *phase;
    int off = 0;
    const int sc[3] = {1, 2, 4};
    for (int k = 0; k < 3; k++) {
        int s = sc[k];
        int j = ph % s;
        g_slot[k] = off + j;
        off += s;
        int alpha = 4 / s;
        for (int i = 0; i < 4; i++) {
            int p = (i + alpha * j) & 3;
            g_invp[k][p] = i;
        }
    }
}

// ---------------- f32 -> f16 packing copy ----------------
__global__ void k_tohalf(const float2* __restrict__ src, __half2* __restrict__ dst, int n2) {
    int i = blockIdx.x * blockDim.x + threadIdx.x;
    if (i < n2) {
        float2 v = src[i];
        dst[i] = __floats2half2_rn(v.x, v.y);
    }
}

// ---------------- block reductions ----------------
template<int W>
__device__ __forceinline__ float block_sum(float x, float* red) {
#pragma unroll
    for (int o = 16; o > 0; o >>= 1) x += __shfl_xor_sync(0xffffffffu, x, o);
    __syncthreads();
    if ((threadIdx.x & 31) == 0) red[threadIdx.x >> 5] = x;
    __syncthreads();
    float s = 0.f;
#pragma unroll
    for (int i = 0; i < W; i++) s += red[i];
    return s;
}
template<int W>
__device__ __forceinline__ float block_max(float x, float* red) {
#pragma unroll
    for (int o = 16; o > 0; o >>= 1) x = fmaxf(x, __shfl_xor_sync(0xffffffffu, x, o));
    __syncthreads();
    if ((threadIdx.x & 31) == 0) red[threadIdx.x >> 5] = x;
    __syncthreads();
    float s = -1e30f;
#pragma unroll
    for (int i = 0; i < W; i++) s = fmaxf(s, red[i]);
    return s;
}

// ---------------- epilogue functors ----------------
struct EpiH {
    __device__ void operator()(int m, int n, int, float v) const { g_h[m*RNK + n] = __float2half_rn(v); }
};
struct EpiBase {
    __device__ void operator()(int m, int n, int, float v) const {
        size_t base = (size_t)m * NDD + n;
        g_z1[base] = v; g_z1[base + DD] = v; g_z1[base + 2*DD] = v; g_z1[base + 3*DD] = v;
    }
};
struct EpiDelta {
    __device__ void operator()(int m, int n, int, float v) const {
        g_z1[(size_t)m * NDD + n] += g_beta * v;
    }
};
struct EpiQKV {
    __device__ void operator()(int m, int n, int bz, float v) const {
        int b = m >> 10, t = m & 1023;
        int kk = bz >> 2, ns = bz & 3;
        int h = g_invp[kk][ns] * 3 + kk;
        __half* dst; int e = n;
        if (e < DH)            { dst = g_q; }
        else if (e < 2*DH)     { dst = g_k; e -= DH; }
        else                   { dst = g_v; e -= 2*DH; }
        dst[(((size_t)b * NH + h) * TT + t) * DH + e] = __float2half_rn(v);
    }
};
struct EpiScore {
    __device__ void operator()(int m, int n, int bz, float v) const {
        g_sc[((size_t)bz * TT + m) * TT + n] =
            (n <= m) ? v * 0.088388347648318447f : -1e9f;
    }
};
struct EpiPV {
    __device__ void operator()(int m, int n, int bz, float v) const {
        int b = bz / NH, h = bz % NH;
        int kk = h % 3, nn = h / 3;
        int slot = g_slot[kk];
        g_z1[(((size_t)(b * TT + m)) * N4 + nn) * DD + slot * DH + n] += v;
    }
};
struct EpiGelu {
    const float* b1;
    __device__ void operator()(int m, int n, int, float v) const {
        float u = v + b1[n];
        g_hidden[(size_t)m * HID + n] =
            __float2half_rn(0.5f * u * (1.f + erff(u * 0.70710678118654752f)));
    }
};
struct EpiMix2 {
    const float* b2;
    __device__ void operator()(int m, int n, int, float v) const {
        g_z1[(size_t)m * DD + n] += v + b2[n];
    }
};
struct EpiDecD {
    __device__ void operator()(int m, int n, int, float v) const { g_dec[m*RNK + n] = v; }
};
struct EpiOut {
    float* out;
    __device__ void operator()(int m, int n, int, float v) const { out[(size_t)m * IOD + n] = v; }
};

// ================= fp16 HMMA GEMM, cp.async 3-stage, ldmatrix frags =================
// C[M,N] = A @ op(B); A row-major MxK fp16. BT_=true: B row-major NxK; BT_=false: B KxN.
// CTA tile 128x128, BK=32, 4 warps (warp tile 64x64), 2 CTAs/SM.
// Requires: M%128==0, N%128==0, Kd%32==0, lda/ldb in halves with 16B-aligned rows.
// A/B-NT smem rows: 40 halves (80B pitch, ldmatrix conflict-free).
// B-NN smem rows: 200 halves (400B pitch, conflict-free for trans-ldmatrix).
#define HG_ABYTES 10240            // 128 rows * 80B
#define HG_BBYTES 12800            // 32 rows * 400B (NN worst case; NT uses 10240)
#define HG_STAGE  (HG_ABYTES + HG_BBYTES)
#define HG_SMEM   (3*HG_STAGE)     // 69120 B

template<bool BT_, bool CSKIP, bool CKLIM, class Epi>
__global__ void __launch_bounds__(128, 2)
hgemm(const __half* __restrict__ A, const __half* __restrict__ B,
      int M, int N, int Kd, int lda, int ldb, long sA, long sB, Epi epi)
{
    extern __shared__ char hsm[];
    const int bz = blockIdx.z;
    A += (size_t)bz * sA;
    B += (size_t)bz * sB;
    const int m0 = blockIdx.y * 128, n0 = blockIdx.x * 128;
    const int tid = threadIdx.x;
    const int lane = tid & 31, wid = tid >> 5;
    const int wm = (wid & 1) * 64, wn = (wid >> 1) * 64;

    float c[32][4];
#pragma unroll
    for (int i = 0; i < 32; i++)
#pragma unroll
        for (int j = 0; j < 4; j++) c[i][j] = 0.f;

    if (!(CSKIP && n0 >= m0 + 128)) {
        int kEnd = CKLIM ? ((Kd < m0 + 128) ? Kd : (m0 + 128)) : Kd;
        int ntile = kEnd >> 5;

        auto issue = [&](int t) {
            uint32_t as_b = (uint32_t)__cvta_generic_to_shared(hsm + (t % 3) * HG_STAGE);
            uint32_t bs_b = as_b + HG_ABYTES;
            int k0 = t * 32;
            const __half* Ap = A + (size_t)(m0 + tid) * lda + k0;
#pragma unroll
            for (int i = 0; i < 4; i++)
                cp16(as_b + (uint32_t)tid * 80 + i * 16, Ap + i * 8);
            if (BT_) {
                const __half* Bp = B + (size_t)(n0 + tid) * ldb + k0;
#pragma unroll
                for (int i = 0; i < 4; i++)
                    cp16(bs_b + (uint32_t)tid * 80 + i * 16, Bp + i * 8);
            } else {
                int r = tid >> 2, c0 = tid & 3;
                const __half* Bp = B + (size_t)(k0 + r) * ldb + n0;
#pragma unroll
                for (int i = 0; i < 4; i++) {
                    int ch = c0 + i * 4;
                    cp16(bs_b + (uint32_t)r * 400 + ch * 16, Bp + ch * 8);
                }
            }
            asm volatile("cp.async.commit_group;\n" ::);
        };

        int npro = ntile < 2 ? ntile : 2;
        for (int s = 0; s < npro; s++) issue(s);

        const int g = lane >> 3, ri = lane & 7;
        for (int t = 0; t < ntile; t++) {
            if (t == ntile - 1) asm volatile("cp.async.wait_group 0;\n" ::: "memory");
            else                asm volatile("cp.async.wait_group 1;\n" ::: "memory");
            __syncthreads();
            if (t + 2 < ntile) issue(t + 2);

            uint32_t as_b = (uint32_t)__cvta_generic_to_shared(hsm + (t % 3) * HG_STAGE);
            uint32_t bs_b = as_b + HG_ABYTES;
#pragma unroll
            for (int ks = 0; ks < 2; ks++) {
                uint32_t a[4][4], b[8][2];
#pragma unroll
                for (int mt = 0; mt < 4; mt++) {
                    uint32_t ad = as_b + (uint32_t)(wm + mt * 16 + (g & 1) * 8 + ri) * 80
                                       + ks * 32 + (g >> 1) * 16;
                    ldsm4(a[mt], ad);
                }
#pragma unroll
                for (int np = 0; np < 4; np++) {
                    uint32_t rr[4];
                    if (BT_) {
                        uint32_t bd = bs_b + (uint32_t)(wn + np * 16 + (g & 1) * 8 + ri) * 80
                                           + ks * 32 + (g >> 1) * 16;
                        ldsm4(rr, bd);
                    } else {
                        uint32_t bd = bs_b + (uint32_t)(ks * 16 + (g >> 1) * 8 + ri) * 400
                                           + (uint32_t)(wn + np * 16 + (g & 1) * 8) * 2;
                        ldsm4t(rr, bd);
                    }
                    b[2*np][0] = rr[0]; b[2*np+1][0] = rr[1];
                    b[2*np][1] = rr[2]; b[2*np+1][1] = rr[3];
                }
#pragma unroll
                for (int mt = 0; mt < 4; mt++)
#pragma unroll
                    for (int nt = 0; nt < 8; nt++)
                        mma_f16(c[mt * 8 + nt], a[mt], b[nt]);
            }
        }
    }
    // ---- epilogue ----
#pragma unroll
    for (int mt = 0; mt < 4; mt++)
#pragma unroll
        for (int nt = 0; nt < 8; nt++)
#pragma unroll
            for (int r = 0; r < 4; r++) {
                int gm = m0 + wm + mt * 16 + (lane >> 2) + (r >> 1) * 8;
                int gn = n0 + wn + nt * 8 + (lane & 3) * 2 + (r & 1);
                epi(gm, gn, bz, c[mt * 8 + nt][r]);
            }
}

// ================= register-prefetch tf32 GEMM (N=64 dec-down) =================
template<bool BT_, class Epi>
__global__ void __launch_bounds__(256, 2)
tgemm(const float* __restrict__ A, const float* __restrict__ B,
      int M, int N, int Kd, int lda, int ldb, long sA, long sB, Epi epi)
{
    const int bz = blockIdx.z;
    A += (size_t)bz * sA;
    B += (size_t)bz * sB;
    const int m0 = blockIdx.y * 128, n0 = blockIdx.x * 128;
    const int tid = threadIdx.x;
    const int lane = tid & 31, wid = tid >> 5;
    const int wm = (wid & 1) * 64, wn = (wid >> 1) * 32;

    __shared__ uint32_t As[128][36];
    __shared__ uint32_t Bs[128][36];

    float c[16][4];
#pragma unroll
    for (int i = 0; i < 16; i++)
#pragma unroll
        for (int j = 0; j < 4; j++) c[i][j] = 0.f;

    {
        int kEnd = Kd;
        const int arw = tid >> 3, aq = (tid & 7) * 4;
        float4 ra[4];
        float  rb[16];
        {
#pragma unroll
            for (int i = 0; i < 4; i++)
                ra[i] = *(const float4*)(A + (size_t)(m0 + arw + i * 32) * lda + aq);
#pragma unroll
            for (int i = 0; i < 4; i++) {
                int gn = n0 + arw + i * 32;
                float4 f = (gn < N) ? *(const float4*)(B + (size_t)gn * ldb + aq)
                                    : make_float4(0.f, 0.f, 0.f, 0.f);
                rb[i*4+0] = f.x; rb[i*4+1] = f.y; rb[i*4+2] = f.z; rb[i*4+3] = f.w;
            }
        }
        for (int k0 = 0; k0 < kEnd; k0 += 32) {
#pragma unroll
            for (int i = 0; i < 4; i++) {
                uint4 u;
                u.x = f2tf(ra[i].x); u.y = f2tf(ra[i].y);
                u.z = f2tf(ra[i].z); u.w = f2tf(ra[i].w);
                *(uint4*)&As[arw + i * 32][aq] = u;
            }
#pragma unroll
            for (int i = 0; i < 4; i++) {
                uint4 u;
                u.x = f2tf(rb[i*4+0]); u.y = f2tf(rb[i*4+1]);
                u.z = f2tf(rb[i*4+2]); u.w = f2tf(rb[i*4+3]);
                *(uint4*)&Bs[arw + i * 32][aq] = u;
            }
            __syncthreads();
            if (k0 + 32 < kEnd) {
                int kn = k0 + 32;
#pragma unroll
                for (int i = 0; i < 4; i++)
                    ra[i] = *(const float4*)(A + (size_t)(m0 + arw + i * 32) * lda + kn + aq);
#pragma unroll
                for (int i = 0; i < 4; i++) {
                    int gn = n0 + arw + i * 32;
                    float4 f = (gn < N) ? *(const float4*)(B + (size_t)gn * ldb + kn + aq)
                                        : make_float4(0.f, 0.f, 0.f, 0.f);
                    rb[i*4+0] = f.x; rb[i*4+1] = f.y; rb[i*4+2] = f.z; rb[i*4+3] = f.w;
                }
            }
#pragma unroll
            for (int ks = 0; ks < 4; ks++) {
                int kk = ks * 8;
                uint32_t a[4][4], b[4][2];
                int ar = lane >> 2, ac = kk + (lane & 3);
#pragma unroll
                for (int mt = 0; mt < 4; mt++) {
                    int row = wm + mt * 16 + ar;
                    a[mt][0] = As[row][ac];
                    a[mt][1] = As[row + 8][ac];
                    a[mt][2] = As[row][ac + 4];
                    a[mt][3] = As[row + 8][ac + 4];
                }
#pragma unroll
                for (int nt = 0; nt < 4; nt++) {
                    int col = wn + nt * 8 + ar;
                    b[nt][0] = Bs[col][ac];
                    b[nt][1] = Bs[col][ac + 4];
                }
#pragma unroll
                for (int mt = 0; mt < 4; mt++)
#pragma unroll
                    for (int nt = 0; nt < 4; nt++)
                        mma_tf32(c[mt * 4 + nt], a[mt], b[nt]);
            }
            __syncthreads();
        }
    }
#pragma unroll
    for (int mt = 0; mt < 4; mt++)
#pragma unroll
        for (int nt = 0; nt < 4; nt++)
#pragma unroll
            for (int r = 0; r < 4; r++) {
                int gm = m0 + wm + mt * 16 + (lane >> 2) + (r >> 1) * 8;
                int gn = n0 + wn + nt * 8 + (lane & 3) * 2 + (r & 1);
                if (gn < N) epi(gm, gn, bz, c[mt * 4 + nt][r]);
            }
}

// ---------------- fp32 tiled GEMM ----------------
template<bool BT_, class Epi>
__global__ void __launch_bounds__(256, 2)
gemm(const float* __restrict__ A, const float* __restrict__ B,
     int M, int N, int Kd, int lda, int ldb, long sA, long sB, Epi epi)
{
    const int bz = blockIdx.z;
    A += (size_t)bz * sA;
    B += (size_t)bz * sB;
    const int m0 = blockIdx.y * 128, n0 = blockIdx.x * 128;
    const int tid = threadIdx.x, tx = tid & 15, ty = tid >> 4;

    __shared__ float As[16][132];
    __shared__ float Bs[16][132];

    float acc[8][8];
#pragma unroll
    for (int i = 0; i < 8; i++)
#pragma unroll
        for (int j = 0; j < 8; j++) acc[i][j] = 0.f;

    for (int k0 = 0; k0 < Kd; k0 += 16) {
#pragma unroll
        for (int i = 0; i < 8; i++) {
            int idx = i * 256 + tid;
            int mm = idx >> 4, kk = idx & 15;
            int gm = m0 + mm, gk = k0 + kk;
            As[kk][mm] = (gm < M && gk < Kd) ? A[(size_t)gm * lda + gk] : 0.f;
        }
        if (BT_) {
#pragma unroll
            for (int i = 0; i < 8; i++) {
                int idx = i * 256 + tid;
                int nn = idx >> 4, kk = idx & 15;
                int gn = n0 + nn, gk = k0 + kk;
                Bs[kk][nn] = (gn < N && gk < Kd) ? B[(size_t)gn * ldb + gk] : 0.f;
            }
        } else {
#pragma unroll
            for (int i = 0; i < 8; i++) {
                int idx = i * 256 + tid;
                int nn = idx & 127, kk = idx >> 7;
                int gn = n0 + nn, gk = k0 + kk;
                Bs[kk][nn] = (gn < N && gk < Kd) ? B[(size_t)gk * ldb + gn] : 0.f;
            }
        }
        __syncthreads();
#pragma unroll
        for (int kk = 0; kk < 16; kk++) {
            float a[8], b[8];
#pragma unroll
            for (int i = 0; i < 8; i++) a[i] = As[kk][ty * 8 + i];
#pragma unroll
            for (int j = 0; j < 8; j++) b[j] = Bs[kk][tx * 8 + j];
#pragma unroll
            for (int i = 0; i < 8; i++)
#pragma unroll
                for (int j = 0; j < 8; j++) acc[i][j] = fmaf(a[i], b[j], acc[i][j]);
        }
        __syncthreads();
    }
#pragma unroll
    for (int i = 0; i < 8; i++) {
        int gm = m0 + ty * 8 + i;
        if (gm >= M) continue;
#pragma unroll
        for (int j = 0; j < 8; j++) {
            int gn = n0 + tx * 8 + j;
            if (gn < N) epi(gm, gn, bz, acc[i][j]);
        }
    }
}

// ---------------- LN over 128 per (bt, k, n) -> x_head (fp16 out) ----------------
__global__ void k_ln_head(const float* __restrict__ sc, const float* __restrict__ bi) {
    int bt = blockIdx.x, z = blockIdx.y;
    int kk = z >> 2, n = z & 3;
    int ns = g_invp[kk][n];
    int slot = g_slot[kk];
    const float* src = g_z1 + ((size_t)bt * 4 + ns) * DD + slot * DH;
    int tid = threadIdx.x;
    __shared__ float red[4];
    float v = src[tid];
    float mu = block_sum<4>(v, red) * (1.f / 128.f);
    float d = v - mu;
    float var = block_sum<4>(d * d, red) * (1.f / 128.f);
    g_xhh[((size_t)bt * NH + z) * DH + tid] =
        __float2half_rn(d * rsqrtf(var + EPSF) * sc[tid] + bi[tid]);
}

// ---------------- row softmax over 1024 (fp16 probs out) ----------------
__global__ void k_softmax() {
    __shared__ float red[8];
    size_t base = (((size_t)blockIdx.y << 10) + blockIdx.x) << 10;
    const float* p = g_sc + base;
    __half* po = g_ph + base;
    int tid = threadIdx.x;
    float v[4];
#pragma unroll
    for (int i = 0; i < 4; i++) v[i] = p[tid + (i << 8)];
    float mx = fmaxf(fmaxf(v[0], v[1]), fmaxf(v[2], v[3]));
    mx = block_max<8>(mx, red);
    float s = 0.f;
#pragma unroll
    for (int i = 0; i < 4; i++) { v[i] = __expf(v[i] - mx); s += v[i]; }
    s = block_sum<8>(s, red);
    float inv = 1.f / s;
#pragma unroll
    for (int i = 0; i < 4; i++) po[tid + (i << 8)] = __float2half_rn(v[i] * inv);
}

// ---------------- LN over 896 (fp16 out, feeds mixer1) ----------------
__global__ void k_ln_mixer(const float* __restrict__ sc, const float* __restrict__ bi) {
    __shared__ float red[8];
    size_t row = blockIdx.x;
    const float* src = g_z1 + row * DD;
    __half* dst = g_hmh + row * DD;
    int tid = threadIdx.x;
    float v[4];
    float s = 0.f;
#pragma unroll
    for (int i = 0; i < 4; i++) {
        int c = tid + i * 256;
        v[i] = (c < DD) ? src[c] : 0.f;
        s += v[i];
    }
    s = block_sum<8>(s, red);
    float mu = s * (1.f / 896.f);
    float q = 0.f;
#pragma unroll
    for (int i = 0; i < 4; i++) {
        int c = tid + i * 256;
        if (c < DD) { float d = v[i] - mu; q += d * d; }
    }
    q = block_sum<8>(q, red);
    float r = rsqrtf(q * (1.f / 896.f) + EPSF);
#pragma unroll
    for (int i = 0; i < 4; i++) {
        int c = tid + i * 256;
        if (c < DD) dst[c] = __float2half_rn((v[i] - mu) * r * sc[c] + bi[c]);
    }
}

// ---------------- LN over 3584 (fp32 out, decoder path) ----------------
__global__ void k_ln_dec(const float* __restrict__ sc, const float* __restrict__ bi) {
    __shared__ float red[8];
    size_t row = blockIdx.x;
    const float* src = g_z1 + row * NDD;
    float* dst = g_hm + row * NDD;
    int tid = threadIdx.x;
    float v[14];
    float s = 0.f;
#pragma unroll
    for (int i = 0; i < 14; i++) { v[i] = src[tid + i * 256]; s += v[i]; }
    s = block_sum<8>(s, red);
    float mu = s * (1.f / 3584.f);
    float q = 0.f;
#pragma unroll
    for (int i = 0; i < 14; i++) { float d = v[i] - mu; q += d * d; }
    q = block_sum<8>(q, red);
    float r = rsqrtf(q * (1.f / 3584.f) + EPSF);
#pragma unroll
    for (int i = 0; i < 14; i++) {
        int c = tid + i * 256;
        dst[c] = (v[i] - mu) * r * sc[c] + bi[c];
    }
}

// ---------------- host launch ----------------
static inline void* sym_addr(const void* symbol) {
    void* p = nullptr;
    cudaGetSymbolAddress(&p, symbol);
    return p;
}

extern "C" void kernel_launch(void* const* d_in, const int* in_sizes, int n_in,
                              void* d_out, int out_size) {
    (void)in_sizes; (void)n_in; (void)out_size;
    const float* x          = (const float*)d_in[0];
    const float* enc_base_w = (const float*)d_in[1];
    const float* enc_A_w    = (const float*)d_in[2];
    const float* enc_B      = (const float*)d_in[3];
    const float* enc_beta   = (const float*)d_in[4];
    const float* Wqkv       = (const float*)d_in[5];
    const float* ln_attn_s  = (const float*)d_in[6];
    const float* ln_attn_b  = (const float*)d_in[7];
    const float* ln_mix_s   = (const float*)d_in[8];
    const float* ln_mix_b   = (const float*)d_in[9];
    const float* w1         = (const float*)d_in[10];
    const float* b1         = (const float*)d_in[11];
    const float* w2         = (const float*)d_in[12];
    const float* b2         = (const float*)d_in[13];
    const float* dls        = (const float*)d_in[14];
    const float* dlb        = (const float*)d_in[15];
    const float* down       = (const float*)d_in[16];
    const float* up         = (const float*)d_in[17];
    const int*   phase      = (const int*)d_in[18];
    float* out = (float*)d_out;

    __half* p_h   = (__half*)sym_addr(g_h);
    float*  p_hm  = (float*) sym_addr(g_hm);
    __half* p_hmh = (__half*)sym_addr(g_hmh);
    __half* p_hid = (__half*)sym_addr(g_hidden);
    __half* p_xhh = (__half*)sym_addr(g_xhh);
    __half* p_q   = (__half*)sym_addr(g_q);
    __half* p_k   = (__half*)sym_addr(g_k);
    __half* p_v   = (__half*)sym_addr(g_v);
    __half* p_ph  = (__half*)sym_addr(g_ph);
    float*  p_dec = (float*) sym_addr(g_dec);
    __half* p_xH  = (__half*)sym_addr(g_xH);
    __half* p_wbH = (__half*)sym_addr(g_wbH);
    __half* p_ebH = (__half*)sym_addr(g_ebH);
    __half* p_wqH = (__half*)sym_addr(g_wqH);
    __half* p_w1H = (__half*)sym_addr(g_w1H);
    __half* p_w2H = (__half*)sym_addr(g_w2H);

    // dynamic smem caps (idempotent)
    cudaFuncSetAttribute(hgemm<true,  false, false, EpiBase >, cudaFuncAttributeMaxDynamicSharedMemorySize, HG_SMEM);
    cudaFuncSetAttribute(hgemm<false, false, false, EpiDelta>, cudaFuncAttributeMaxDynamicSharedMemorySize, HG_SMEM);
    cudaFuncSetAttribute(hgemm<false, false, false, EpiQKV  >, cudaFuncAttributeMaxDynamicSharedMemorySize, HG_SMEM);
    cudaFuncSetAttribute(hgemm<true,  true,  false, EpiScore>, cudaFuncAttributeMaxDynamicSharedMemorySize, HG_SMEM);
    cudaFuncSetAttribute(hgemm<false, false, true,  EpiPV   >, cudaFuncAttributeMaxDynamicSharedMemorySize, HG_SMEM);
    cudaFuncSetAttribute(hgemm<true,  false, false, EpiGelu >, cudaFuncAttributeMaxDynamicSharedMemorySize, HG_SMEM);
    cudaFuncSetAttribute(hgemm<true,  false, false, EpiMix2 >, cudaFuncAttributeMaxDynamicSharedMemorySize, HG_SMEM);

    // 0. scalars + phase tables
    k_scalars<<<1, 1>>>(enc_beta, phase);

    // 0b. fp16 packing of external gemm inputs
    k_tohalf<<<(BTOK*IOD/2 + 255)/256, 256>>>((const float2*)x,          (__half2*)p_xH,  BTOK*IOD/2);
    k_tohalf<<<(DD*IOD/2   + 255)/256, 256>>>((const float2*)enc_base_w, (__half2*)p_wbH, DD*IOD/2);
    k_tohalf<<<(RNK*NDD/2  + 255)/256, 256>>>((const float2*)enc_B,      (__half2*)p_ebH, RNK*NDD/2);
    k_tohalf<<<(K3*N4*DH*3*DH/2 + 255)/256, 256>>>((const float2*)Wqkv,  (__half2*)p_wqH, K3*N4*DH*3*DH/2);
    k_tohalf<<<((size_t)HID*DD/2 + 255)/256, 256>>>((const float2*)w1,   (__half2*)p_w1H, HID*DD/2);
    k_tohalf<<<((size_t)DD*HID/2 + 255)/256, 256>>>((const float2*)w2,   (__half2*)p_w2H, DD*HID/2);

    // 1. h = x @ enc_A_w.T  (fp32 compute; epilogue packs fp16)
    gemm<true><<<dim3(1, 64, 1), 256>>>(
        x, enc_A_w, BTOK, RNK, IOD, IOD, IOD, 0, 0, EpiH{});

    // 2. base = x @ enc_base_w.T -> broadcast to z0  (fp16 NT)
    hgemm<true, false, false><<<dim3(7, 64, 1), 128, HG_SMEM>>>(
        p_xH, p_wbH, BTOK, DD, IOD, IOD, IOD, 0, 0, EpiBase{});

    // 3. z0 += beta * (h @ enc_B)  (fp16 NN)
    hgemm<false, false, false><<<dim3(28, 64, 1), 128, HG_SMEM>>>(
        p_h, p_ebH, BTOK, NDD, RNK, RNK, NDD, 0, 0, EpiDelta{});

    // 4. LN over slot heads -> x_head (fp16)
    k_ln_head<<<dim3(BTOK, NH), 128>>>(ln_attn_s, ln_attn_b);

    // 5. qkv (fp16 NN, batched 12)
    hgemm<false, false, false><<<dim3(3, 64, 12), 128, HG_SMEM>>>(
        p_xhh, p_wqH, BTOK, 3 * DH, DH, NH * DH, 3 * DH,
        (long)DH, (long)DH * 3 * DH, EpiQKV{});

    // 6. scores (fp16 NT, causal skip) -> fp32 g_sc
    hgemm<true, true, false><<<dim3(8, 8, BB * NH), 128, HG_SMEM>>>(
        p_q, p_k, TT, TT, DH, DH, DH,
        (long)TT * DH, (long)TT * DH, EpiScore{});

    // 7. softmax -> fp16 probs
    k_softmax<<<dim3(TT, BB * NH), 256>>>();

    // 8. out = P @ V (fp16 NN, causal k-clip) -> accumulate z1
    hgemm<false, false, true><<<dim3(1, 8, BB * NH), 128, HG_SMEM>>>(
        p_ph, p_v, TT, DH, TT, TT, DH,
        (long)TT * TT, (long)TT * DH, EpiPV{});

    // 9. mixer LN -> fp16
    k_ln_mixer<<<dim3(BTOK * N4), 256>>>(ln_mix_s, ln_mix_b);

    // 10. hidden = gelu(hm @ w1.T + b1)  (fp16 NT)
    hgemm<true, false, false><<<dim3(28, 256, 1), 128, HG_SMEM>>>(
        p_hmh, p_w1H, BTOK * N4, HID, DD, DD, DD, 0, 0, EpiGelu{b1});

    // 11. z2 = z1 + hidden @ w2.T + b2  (fp16 NT)
    hgemm<true, false, false><<<dim3(7, 256, 1), 128, HG_SMEM>>>(
        p_hid, p_w2H, BTOK * N4, DD, HID, HID, HID, 0, 0, EpiMix2{b2});

    // 12. decoder LN (fp32)
    k_ln_dec<<<dim3(BTOK), 256>>>(dls, dlb);

    // 13. dec = catln @ down.T  (tf32 NT, N=64 guarded)
    tgemm<true><<<dim3(1, 64, 1), 256>>>(
        p_hm, down, BTOK, RNK, NDD, NDD, NDD, 0, 0, EpiDecD{});

    // 14. y = dec @ up.T  (fp32, final output, tiny K)
    gemm<true><<<dim3(8, 64, 1), 256>>>(
        p_dec, up, BTOK, IOD, RNK, RNK, RNK, 0, 0, EpiOut{out});
}